// round 8
// baseline (speedup 1.0000x reference)
#include <cuda_runtime.h>
#include <cuda_fp16.h>
#include <cstdint>

// ---------------- scratch (__device__ globals; no allocation) ----------------
// layout: [img][ocGroup 0..3][px 0..1023][8 words of 16 fp16 ch]
__device__ uint32_t g_a32[1024 * 32768];   // conv1 output (134MB)
__device__ float g_pool[1024 * 128];       // pooled conv2 features

// ---------------- helpers ----------------
__device__ __forceinline__ uint32_t smem_u32(const void* p) {
    uint32_t a;
    asm("{ .reg .u64 t; cvta.to.shared.u64 t, %1; cvt.u32.u64 %0, t; }" : "=r"(a) : "l"(p));
    return a;
}
__device__ __forceinline__ uint32_t pack_h2(float a, float b) {
    __half2 t = __floats2half2_rn(a, b);
    return *reinterpret_cast<uint32_t*>(&t);
}
__device__ __forceinline__ void ldmx4(uint32_t& r0, uint32_t& r1, uint32_t& r2, uint32_t& r3,
                                      uint32_t addr) {
    asm volatile("ldmatrix.sync.aligned.m8n8.x4.shared.b16 {%0,%1,%2,%3}, [%4];"
                 : "=r"(r0), "=r"(r1), "=r"(r2), "=r"(r3) : "r"(addr));
}
__device__ __forceinline__ void mma16816(float* c, const uint32_t* a, uint32_t b0, uint32_t b1) {
    asm volatile(
        "mma.sync.aligned.m16n8k16.row.col.f32.f16.f16.f32 "
        "{%0,%1,%2,%3}, {%4,%5,%6,%7}, {%8,%9}, {%0,%1,%2,%3};"
        : "+f"(c[0]), "+f"(c[1]), "+f"(c[2]), "+f"(c[3])
        : "r"(a[0]), "r"(a[1]), "r"(a[2]), "r"(a[3]), "r"(b0), "r"(b1));
}

// ---------------- conv1 (3->64, 3x3 SAME) + ReLU -> grouped NHWC fp16 ----------------
// dynamic smem: sIn 3072f | sW 1728f | sB 64f | stage 9216 words = 56320 bytes
static constexpr int C1_SMEM = 56320;

__global__ __launch_bounds__(256) void conv1_kernel(const float* __restrict__ x,
                                                    const float* __restrict__ w,
                                                    const float* __restrict__ bias) {
    extern __shared__ float c1s[];
    float* sIn = c1s;                  // 3072
    float* sW  = c1s + 3072;           // 1728  [kt][oc]
    float* sB  = c1s + 4800;           // 64
    uint32_t* stage = reinterpret_cast<uint32_t*>(c1s + 4864);  // 1024 px * 9 words

    int img = blockIdx.x, tid = threadIdx.x;
    for (int j = tid; j < 3072; j += 256) sIn[j] = x[img * 3072 + j];
    for (int e = tid; e < 1728; e += 256) { int k = e >> 6, o = e & 63; sW[e] = w[o * 27 + k]; }
    if (tid < 64) sB[tid] = bias[tid];
    __syncthreads();
    int r = tid >> 3, x0 = (tid & 7) << 2;

    for (int oc0 = 0; oc0 < 64; oc0 += 16) {
        float acc[4][16];
#pragma unroll
        for (int p = 0; p < 4; p++)
#pragma unroll
            for (int o = 0; o < 16; o++) acc[p][o] = sB[oc0 + o];
#pragma unroll
        for (int ic = 0; ic < 3; ic++) {
#pragma unroll
            for (int ky = 0; ky < 3; ky++) {
                int yy = r + ky - 1;
                float iv[6];
                if ((unsigned)yy < 32u) {
                    const float* row = sIn + ic * 1024 + yy * 32;
#pragma unroll
                    for (int j = 0; j < 6; j++) {
                        int xx = x0 - 1 + j;
                        iv[j] = ((unsigned)xx < 32u) ? row[xx] : 0.f;
                    }
                } else {
#pragma unroll
                    for (int j = 0; j < 6; j++) iv[j] = 0.f;
                }
#pragma unroll
                for (int kx = 0; kx < 3; kx++) {
                    const float* wp = sW + (ic * 9 + ky * 3 + kx) * 64 + oc0;
                    float wv[16];
#pragma unroll
                    for (int o = 0; o < 16; o++) wv[o] = wp[o];
#pragma unroll
                    for (int p = 0; p < 4; p++) {
                        float v = iv[p + kx];
#pragma unroll
                        for (int o = 0; o < 16; o++) acc[p][o] = fmaf(v, wv[o], acc[p][o]);
                    }
                }
            }
        }
        // stage (XOR-swizzled, conflict-free) then flush coalesced
        __syncthreads();   // previous group's flush readers done
#pragma unroll
        for (int p = 0; p < 4; p++) {
            int pix = r * 32 + x0 + p;
            int xr = (pix >> 5) & 7;
            uint32_t* st = stage + pix * 9;
#pragma unroll
            for (int oo = 0; oo < 8; oo++)
                st[oo ^ xr] = pack_h2(fmaxf(acc[p][2 * oo], 0.f),
                                      fmaxf(acc[p][2 * oo + 1], 0.f));
        }
        __syncthreads();
        {
            int g = oc0 >> 4;
            uint4* dst = reinterpret_cast<uint4*>(g_a32 + (size_t)img * 32768 + g * 8192);
            int px0 = tid >> 1, w0 = (tid & 1) * 4;
#pragma unroll
            for (int k4 = 0; k4 < 8; k4++) {
                int px = px0 + k4 * 128;
                int xr = (px >> 5) & 7;
                const uint32_t* st = stage + px * 9;
                uint4 v;
                v.x = st[(w0 + 0) ^ xr];
                v.y = st[(w0 + 1) ^ xr];
                v.z = st[(w0 + 2) ^ xr];
                v.w = st[(w0 + 3) ^ xr];
                dst[tid + k4 * 256] = v;
            }
        }
    }
}

// ---------------- conv2 via mma.sync fp16 + ring-buffered cp.async + ReLU + pool --------
// SMEM: B 149504 | A ring 14 slots x 34px x 144B = 68544 | bias 512 | pool 2048
static constexpr int B_OFF = 0;
static constexpr int SIN_OFF = 149504;
static constexpr int SBIAS_OFF = 218048;
static constexpr int SPOOL_OFF = 218560;
static constexpr int SMEM2_TOTAL = 220608;

__device__ __forceinline__ void c2_load_rows(uint32_t sbase, const uint32_t* gsrc,
                                             int y0, int nrows, int slot0, int tid) {
    int chunks = nrows * 256;   // 32px * 4g * 2q per row
    for (int c = tid; c < chunks; c += 512) {
        int rr = c >> 8, rem = c & 255;
        int px = rem >> 3, g = (rem >> 1) & 3, q = rem & 1;
        int y = y0 + rr;
        int slot = slot0 + rr; if (slot >= 14) slot -= 14;
        uint32_t ok = ((unsigned)y < 32u) ? 16u : 0u;
        int yc = y < 0 ? 0 : (y > 31 ? 31 : y);
        const void* src = gsrc + g * 8192 + (yc * 32 + px) * 8 + q * 4;
        uint32_t sd = sbase + SIN_OFF +
                      (uint32_t)(slot * 4896 + (px + 1) * 144 + g * 32 + q * 16);
        asm volatile("cp.async.cg.shared.global [%0], [%1], 16, %2;"
                     :: "r"(sd), "l"(src), "r"(ok) : "memory");
    }
}

__global__ __launch_bounds__(512, 1) void conv2_mma_kernel(const float* __restrict__ w,
                                                           const float* __restrict__ bias) {
    extern __shared__ __align__(16) char smem[];
    uint32_t sbase = smem_u32(smem);
    float* sBias = reinterpret_cast<float*>(smem + SBIAS_OFF);
    float* sPool = reinterpret_cast<float*>(smem + SPOOL_OFF);
    int tid = threadIdx.x, lane = tid & 31, wid = tid >> 5;
    int m_idx = wid & 3, n_idx = wid >> 2;   // 4 m-warps (64px) x 4 n-warps (32oc)

    // zero x-halo columns (px slots 0 and 33) of all 14 ring slots
    for (int e = tid; e < 1008; e += 512) {
        int slot = e / 72, rem = e % 72;
        int side = rem / 36, q = rem % 36;
        *reinterpret_cast<uint32_t*>(smem + SIN_OFF + slot * 4896 + (side ? 33 : 0) * 144 + q * 4) = 0u;
    }
    // build B: sB[n][k], k = s*64 + ic, k-stride padded to 584 elems (fp16)
    for (int e = tid; e < 73728; e += 512) {
        int n = e / 576, k = e - n * 576;
        int ic = k & 63, s = k >> 6;
        float v = w[n * 576 + ic * 9 + s];
        *reinterpret_cast<__half*>(smem + B_OFF + (n * 584 + k) * 2) = __float2half(v);
    }
    if (tid < 128) sBias[tid] = bias[tid];
    __syncthreads();

    uint32_t aThr = (uint32_t)((lane & 15) * 144 + ((lane >> 4) & 1) * 16);
    uint32_t bThr = (uint32_t)(((((lane >> 4) & 1) * 8 + (lane & 7)) * 584 +
                                ((lane >> 3) & 1) * 8) * 2 + n_idx * 37376);
    float bv[4][2];
#pragma unroll
    for (int j = 0; j < 4; j++) {
        bv[j][0] = sBias[n_idx * 32 + j * 8 + (lane & 3) * 2];
        bv[j][1] = sBias[n_idx * 32 + j * 8 + (lane & 3) * 2 + 1];
    }

    for (int img = blockIdx.x; img < 1024; img += gridDim.x) {
        const uint32_t* gsrc = g_a32 + (size_t)img * 32768;
        // prologue: rows -1..8 -> slots 0..9
        c2_load_rows(sbase, gsrc, -1, 10, 0, tid);
        asm volatile("cp.async.commit_group;" ::: "memory");

        float pool[4][2];
#pragma unroll
        for (int j = 0; j < 4; j++) { pool[j][0] = 0.f; pool[j][1] = 0.f; }

        for (int t = 0; t < 4; t++) {
            if (t < 3) {
                // batch A: 4 rows, hidden under this tile's compute
                c2_load_rows(sbase, gsrc, 8 * t + 9, 4, (8 * t + 10) % 14, tid);
                asm volatile("cp.async.commit_group;" ::: "memory");
                asm volatile("cp.async.wait_group 1;" ::: "memory");
            } else {
                asm volatile("cp.async.wait_group 0;" ::: "memory");
            }
            __syncthreads();

            // per-tile ring slot bases for rows base_row..base_row+3
            int base_row = 8 * t + 2 * m_idx;
            uint32_t sb[4];
#pragma unroll
            for (int j = 0; j < 4; j++) {
                int sl = base_row + j;
                if (sl >= 28) sl -= 28; else if (sl >= 14) sl -= 14;
                sb[j] = (uint32_t)(sl * 4896);
            }

            float acc[4][4][4];
#pragma unroll
            for (int f = 0; f < 4; f++)
#pragma unroll
                for (int j = 0; j < 4; j++)
#pragma unroll
                    for (int q = 0; q < 4; q++) acc[f][j][q] = 0.f;

            uint32_t aBase = sbase + SIN_OFF + aThr;
            uint32_t bBase = sbase + B_OFF + bThr;
#pragma unroll
            for (int s = 0; s < 9; s++) {
                const int ky = s / 3, kx = s % 3;
#pragma unroll
                for (int ks = 0; ks < 4; ks++) {
                    uint32_t a[4][4];
#pragma unroll
                    for (int f = 0; f < 4; f++)
                        ldmx4(a[f][0], a[f][1], a[f][2], a[f][3],
                              aBase + sb[(f >> 1) + ky] +
                              (uint32_t)((f & 1) * 2304 + kx * 144 + ks * 32));
                    uint32_t kofs = (uint32_t)(s * 128 + ks * 32);
#pragma unroll
                    for (int fp = 0; fp < 2; fp++) {
                        uint32_t r0, r1, r2, r3;
                        ldmx4(r0, r1, r2, r3, bBase + (uint32_t)(fp * 18688) + kofs);
#pragma unroll
                        for (int f = 0; f < 4; f++) {
                            mma16816(acc[f][fp * 2], a[f], r0, r1);
                            mma16816(acc[f][fp * 2 + 1], a[f], r2, r3);
                        }
                    }
                }
            }
            // bias + relu + pixel-pool
#pragma unroll
            for (int f = 0; f < 4; f++)
#pragma unroll
                for (int j = 0; j < 4; j++) {
                    pool[j][0] += fmaxf(acc[f][j][0] + bv[j][0], 0.f) +
                                  fmaxf(acc[f][j][2] + bv[j][0], 0.f);
                    pool[j][1] += fmaxf(acc[f][j][1] + bv[j][1], 0.f) +
                                  fmaxf(acc[f][j][3] + bv[j][1], 0.f);
                }
            __syncthreads();
            if (t < 3) {
                // batch B: 4 rows into slots just released by this tile
                c2_load_rows(sbase, gsrc, 8 * t + 13, 4, (8 * t + 14) % 14, tid);
                asm volatile("cp.async.commit_group;" ::: "memory");
            }
        }
        // reduce over lanes with same (lane&3)
#pragma unroll
        for (int off = 4; off <= 16; off <<= 1)
#pragma unroll
            for (int j = 0; j < 4; j++) {
                pool[j][0] += __shfl_xor_sync(0xffffffffu, pool[j][0], off);
                pool[j][1] += __shfl_xor_sync(0xffffffffu, pool[j][1], off);
            }
        if (lane < 4) {
            float* sp = sPool + wid * 32;
#pragma unroll
            for (int j = 0; j < 4; j++) {
                sp[j * 8 + lane * 2] = pool[j][0];
                sp[j * 8 + lane * 2 + 1] = pool[j][1];
            }
        }
        __syncthreads();
        if (tid < 128) {
            int ni = tid >> 5, col = tid & 31;
            float s = 0.f;
#pragma unroll
            for (int m = 0; m < 4; m++) s += sPool[(ni * 4 + m) * 32 + col];
            g_pool[img * 128 + tid] = s * (1.f / 1024.f);
        }
        __syncthreads();
    }
}

// ---------------- fused tail: fc + mask + colsum + sage1 + colsum + sage2 ----------------
static constexpr int TP_POOL = 0;       // 32 x 128
static constexpr int TP_H    = 4096;    // 32 x 256 (reused as sage2 partials)
static constexpr int TP_O1   = 12288;   // 32 x 256
static constexpr int TP_CS   = 20480;   // 256
static constexpr int TP_B2   = 20736;   // 256
static constexpr int TP_MASK = 20992;   // 32
static constexpr int TAIL_SMEM = 21024 * 4;

__global__ __launch_bounds__(256) void tail_kernel(
    const float* __restrict__ fc_w, const float* __restrict__ fc_b,
    const float* __restrict__ mask,
    const float* __restrict__ s1_lw, const float* __restrict__ s1_lb,
    const float* __restrict__ s1_rw,
    const float* __restrict__ s2_lw, const float* __restrict__ s2_lb,
    const float* __restrict__ s2_rw,
    float* __restrict__ out) {
    extern __shared__ float sm[];
    float* sPool = sm + TP_POOL;
    float* sH    = sm + TP_H;
    float* sO1   = sm + TP_O1;
    float* sCs   = sm + TP_CS;
    float* sB2   = sm + TP_B2;
    float* sMask = sm + TP_MASK;
    int b = blockIdx.x, tid = threadIdx.x;

    for (int e = tid; e < 4096; e += 256) sPool[e] = g_pool[b * 4096 + e];
    if (tid < 32) sMask[tid] = mask[b * 32 + tid];
    __syncthreads();

    // fc: thread = output dim o (256); 32 nodes in registers
    {
        float acc[32];
#pragma unroll
        for (int n = 0; n < 32; n++) acc[n] = 0.f;
        const float4* wrow = reinterpret_cast<const float4*>(fc_w + tid * 128);
#pragma unroll 4
        for (int k4 = 0; k4 < 32; k4++) {
            float4 wv = wrow[k4];
#pragma unroll
            for (int n = 0; n < 32; n++) {
                float4 hv = *reinterpret_cast<const float4*>(sPool + n * 128 + k4 * 4);
                acc[n] += wv.x * hv.x + wv.y * hv.y + wv.z * hv.z + wv.w * hv.w;
            }
        }
        float fb = fc_b[tid];
#pragma unroll
        for (int n = 0; n < 32; n++) sH[n * 256 + tid] = (acc[n] + fb) * sMask[n];
    }
    __syncthreads();
    {
        float s = 0.f;
#pragma unroll
        for (int n = 0; n < 32; n++) s += sH[n * 256 + tid];
        sCs[tid] = s;
    }
    __syncthreads();

    // sage1
    {
        float acc[32];
#pragma unroll
        for (int n = 0; n < 32; n++) acc[n] = 0.f;
        float bacc = 0.f;
        const float4* lw4 = reinterpret_cast<const float4*>(s1_lw + tid * 256);
        const float4* rw4 = reinterpret_cast<const float4*>(s1_rw + tid * 256);
#pragma unroll 2
        for (int k4 = 0; k4 < 64; k4++) {
            float4 lw = lw4[k4], rw = rw4[k4];
            float4 cs = *reinterpret_cast<const float4*>(sCs + k4 * 4);
            bacc += cs.x * lw.x + cs.y * lw.y + cs.z * lw.z + cs.w * lw.w;
            float4 wc;
            wc.x = rw.x - lw.x * (1.f / 31.f); wc.y = rw.y - lw.y * (1.f / 31.f);
            wc.z = rw.z - lw.z * (1.f / 31.f); wc.w = rw.w - lw.w * (1.f / 31.f);
#pragma unroll
            for (int n = 0; n < 32; n++) {
                float4 hv = *reinterpret_cast<const float4*>(sH + n * 256 + k4 * 4);
                acc[n] += wc.x * hv.x + wc.y * hv.y + wc.z * hv.z + wc.w * hv.w;
            }
        }
        float base = s1_lb[tid] + bacc * (1.f / 31.f);
#pragma unroll
        for (int n = 0; n < 32; n++) sO1[n * 256 + tid] = fmaxf(base + acc[n], 0.f);
    }
    __syncthreads();
    {
        float s = 0.f;
#pragma unroll
        for (int n = 0; n < 32; n++) s += sO1[n * 256 + tid];
        sCs[tid] = s;
    }
    __syncthreads();

    // sage2: o2 = tid&127, k-half = tid>>7
    {
        int o2 = tid & 127, half = tid >> 7;
        float acc[32];
#pragma unroll
        for (int n = 0; n < 32; n++) acc[n] = 0.f;
        float bacc = 0.f;
        const float4* lw4 = reinterpret_cast<const float4*>(s2_lw + o2 * 256 + half * 128);
        const float4* rw4 = reinterpret_cast<const float4*>(s2_rw + o2 * 256 + half * 128);
        const float* csb = sCs + half * 128;
        const float* o1b = sO1 + half * 128;
#pragma unroll 2
        for (int k4 = 0; k4 < 32; k4++) {
            float4 lw = lw4[k4], rw = rw4[k4];
            float4 cs = *reinterpret_cast<const float4*>(csb + k4 * 4);
            bacc += cs.x * lw.x + cs.y * lw.y + cs.z * lw.z + cs.w * lw.w;
            float4 wc;
            wc.x = rw.x - lw.x * (1.f / 31.f); wc.y = rw.y - lw.y * (1.f / 31.f);
            wc.z = rw.z - lw.z * (1.f / 31.f); wc.w = rw.w - lw.w * (1.f / 31.f);
#pragma unroll
            for (int n = 0; n < 32; n++) {
                float4 hv = *reinterpret_cast<const float4*>(o1b + n * 256 + k4 * 4);
                acc[n] += wc.x * hv.x + wc.y * hv.y + wc.z * hv.z + wc.w * hv.w;
            }
        }
#pragma unroll
        for (int n = 0; n < 32; n++) sH[n * 256 + tid] = acc[n];
        sB2[tid] = bacc;
    }
    __syncthreads();
    for (int e = tid; e < 4096; e += 256) {
        int n = e >> 7, o2 = e & 127;
        float v = sH[n * 256 + o2] + sH[n * 256 + o2 + 128];
        float base = s2_lb[o2] + (sB2[o2] + sB2[o2 + 128]) * (1.f / 31.f);
        out[(b * 32 + n) * 128 + o2] = base + v;
    }
}

// ---------------- launch ----------------
extern "C" void kernel_launch(void* const* d_in, const int* in_sizes, int n_in,
                              void* d_out, int out_size) {
    const float* x       = (const float*)d_in[0];
    const float* mask    = (const float*)d_in[1];
    const float* conv1_w = (const float*)d_in[2];
    const float* conv1_b = (const float*)d_in[3];
    const float* conv2_w = (const float*)d_in[4];
    const float* conv2_b = (const float*)d_in[5];
    const float* fc_w    = (const float*)d_in[6];
    const float* fc_b    = (const float*)d_in[7];
    const float* s1_lw   = (const float*)d_in[8];
    const float* s1_lb   = (const float*)d_in[9];
    const float* s1_rw   = (const float*)d_in[10];
    const float* s2_lw   = (const float*)d_in[11];
    const float* s2_lb   = (const float*)d_in[12];
    const float* s2_rw   = (const float*)d_in[13];
    float* out = (float*)d_out;

    cudaFuncSetAttribute(conv1_kernel, cudaFuncAttributeMaxDynamicSharedMemorySize, C1_SMEM);
    cudaFuncSetAttribute(conv2_mma_kernel, cudaFuncAttributeMaxDynamicSharedMemorySize,
                         SMEM2_TOTAL);
    cudaFuncSetAttribute(tail_kernel, cudaFuncAttributeMaxDynamicSharedMemorySize, TAIL_SMEM);

    conv1_kernel<<<1024, 256, C1_SMEM>>>(x, conv1_w, conv1_b);
    conv2_mma_kernel<<<148, 512, SMEM2_TOTAL>>>(conv2_w, conv2_b);
    tail_kernel<<<32, 256, TAIL_SMEM>>>(fc_w, fc_b, mask, s1_lw, s1_lb, s1_rw,
                                        s2_lw, s2_lb, s2_rw, out);
}

// round 9
// speedup vs baseline: 1.2378x; 1.2378x over previous
#include <cuda_runtime.h>
#include <cuda_fp16.h>
#include <cstdint>

// ---------------- scratch (__device__ globals; no allocation) ----------------
// layout: [img][ocGroup 0..3][px 0..1023][8 words of 16 fp16 ch]
__device__ uint32_t g_a32[1024 * 32768];   // conv1 output (134MB)
__device__ float g_pool[1024 * 128];       // pooled conv2 features

// ---------------- helpers ----------------
__device__ __forceinline__ uint32_t smem_u32(const void* p) {
    uint32_t a;
    asm("{ .reg .u64 t; cvta.to.shared.u64 t, %1; cvt.u32.u64 %0, t; }" : "=r"(a) : "l"(p));
    return a;
}
__device__ __forceinline__ uint32_t pack_h2(float a, float b) {
    __half2 t = __floats2half2_rn(a, b);
    return *reinterpret_cast<uint32_t*>(&t);
}
__device__ __forceinline__ void ldmx4(uint32_t& r0, uint32_t& r1, uint32_t& r2, uint32_t& r3,
                                      uint32_t addr) {
    asm volatile("ldmatrix.sync.aligned.m8n8.x4.shared.b16 {%0,%1,%2,%3}, [%4];"
                 : "=r"(r0), "=r"(r1), "=r"(r2), "=r"(r3) : "r"(addr));
}
__device__ __forceinline__ void mma16816(float* c, const uint32_t* a, uint32_t b0, uint32_t b1) {
    asm volatile(
        "mma.sync.aligned.m16n8k16.row.col.f32.f16.f16.f32 "
        "{%0,%1,%2,%3}, {%4,%5,%6,%7}, {%8,%9}, {%0,%1,%2,%3};"
        : "+f"(c[0]), "+f"(c[1]), "+f"(c[2]), "+f"(c[3])
        : "r"(a[0]), "r"(a[1]), "r"(a[2]), "r"(a[3]), "r"(b0), "r"(b1));
}

// ---------------- conv1 (3->64, 3x3 SAME) + ReLU -> grouped NHWC fp16 ----------------
// dynamic smem: sIn 3072f | sW 1728f | sB 64f | stage 9216 words = 56320 bytes
static constexpr int C1_SMEM = 56320;

__global__ __launch_bounds__(256) void conv1_kernel(const float* __restrict__ x,
                                                    const float* __restrict__ w,
                                                    const float* __restrict__ bias) {
    extern __shared__ float c1s[];
    float* sIn = c1s;                  // 3072
    float* sW  = c1s + 3072;           // 1728  [kt][oc]
    float* sB  = c1s + 4800;           // 64
    uint32_t* stage = reinterpret_cast<uint32_t*>(c1s + 4864);  // 1024 px * 9 words

    int img = blockIdx.x, tid = threadIdx.x;
    for (int j = tid; j < 3072; j += 256) sIn[j] = x[img * 3072 + j];
    for (int e = tid; e < 1728; e += 256) { int k = e >> 6, o = e & 63; sW[e] = w[o * 27 + k]; }
    if (tid < 64) sB[tid] = bias[tid];
    __syncthreads();
    int r = tid >> 3, x0 = (tid & 7) << 2;

    for (int oc0 = 0; oc0 < 64; oc0 += 16) {
        float acc[4][16];
#pragma unroll
        for (int p = 0; p < 4; p++)
#pragma unroll
            for (int o = 0; o < 16; o++) acc[p][o] = sB[oc0 + o];
#pragma unroll
        for (int ic = 0; ic < 3; ic++) {
#pragma unroll
            for (int ky = 0; ky < 3; ky++) {
                int yy = r + ky - 1;
                float iv[6];
                if ((unsigned)yy < 32u) {
                    const float* row = sIn + ic * 1024 + yy * 32;
#pragma unroll
                    for (int j = 0; j < 6; j++) {
                        int xx = x0 - 1 + j;
                        iv[j] = ((unsigned)xx < 32u) ? row[xx] : 0.f;
                    }
                } else {
#pragma unroll
                    for (int j = 0; j < 6; j++) iv[j] = 0.f;
                }
#pragma unroll
                for (int kx = 0; kx < 3; kx++) {
                    const float* wp = sW + (ic * 9 + ky * 3 + kx) * 64 + oc0;
                    float wv[16];
#pragma unroll
                    for (int o = 0; o < 16; o++) wv[o] = wp[o];
#pragma unroll
                    for (int p = 0; p < 4; p++) {
                        float v = iv[p + kx];
#pragma unroll
                        for (int o = 0; o < 16; o++) acc[p][o] = fmaf(v, wv[o], acc[p][o]);
                    }
                }
            }
        }
        // stage (XOR-swizzled, conflict-free) then flush coalesced
        __syncthreads();   // previous group's flush readers done
#pragma unroll
        for (int p = 0; p < 4; p++) {
            int pix = r * 32 + x0 + p;
            int xr = (pix >> 5) & 7;
            uint32_t* st = stage + pix * 9;
#pragma unroll
            for (int oo = 0; oo < 8; oo++)
                st[oo ^ xr] = pack_h2(fmaxf(acc[p][2 * oo], 0.f),
                                      fmaxf(acc[p][2 * oo + 1], 0.f));
        }
        __syncthreads();
        {
            int g = oc0 >> 4;
            uint4* dst = reinterpret_cast<uint4*>(g_a32 + (size_t)img * 32768 + g * 8192);
            int px0 = tid >> 1, w0 = (tid & 1) * 4;
#pragma unroll
            for (int k4 = 0; k4 < 8; k4++) {
                int px = px0 + k4 * 128;
                int xr = (px >> 5) & 7;
                const uint32_t* st = stage + px * 9;
                uint4 v;
                v.x = st[(w0 + 0) ^ xr];
                v.y = st[(w0 + 1) ^ xr];
                v.z = st[(w0 + 2) ^ xr];
                v.w = st[(w0 + 3) ^ xr];
                dst[tid + k4 * 256] = v;
            }
        }
    }
}

// ---------------- conv2 via mma.sync fp16 (R7 structure, grouped src) + ReLU + pool ----
// SMEM: B 149504 | A tile 48960 (10 rows x 34 px x 144B) | bias 512 | pool 2048
static constexpr int B_OFF = 0;
static constexpr int SIN_OFF = 149504;
static constexpr int SBIAS_OFF = 198464;
static constexpr int SPOOL_OFF = 198976;
static constexpr int SMEM2_TOTAL = 201024;

__global__ __launch_bounds__(512, 1) void conv2_mma_kernel(const float* __restrict__ w,
                                                           const float* __restrict__ bias) {
    extern __shared__ __align__(16) char smem[];
    uint32_t sbase = smem_u32(smem);
    float* sBias = reinterpret_cast<float*>(smem + SBIAS_OFF);
    float* sPool = reinterpret_cast<float*>(smem + SPOOL_OFF);
    int tid = threadIdx.x, lane = tid & 31, wid = tid >> 5;
    int m_idx = wid & 3, n_idx = wid >> 2;   // 4 m-warps (64px each) x 4 n-warps (32oc each)

    // zero x-halo pixels (smem px cols 0 and 33), rows 0..9
    for (int e = tid; e < 640; e += 512) {
        int r = e >> 6, side = (e >> 5) & 1, q = e & 31;
        int px = side ? 33 : 0;
        *reinterpret_cast<uint32_t*>(smem + SIN_OFF + r * 4896 + px * 144 + q * 4) = 0u;
    }
    // build B: sB[n][k], k = s*64 + ic, k-stride padded to 584 elems (fp16)
    for (int e = tid; e < 73728; e += 512) {
        int n = e / 576, k = e - n * 576;
        int ic = k & 63, s = k >> 6;
        float v = w[n * 576 + ic * 9 + s];
        *reinterpret_cast<__half*>(smem + B_OFF + (n * 584 + k) * 2) = __float2half(v);
    }
    if (tid < 128) sBias[tid] = bias[tid];
    __syncthreads();

    // per-thread ldmatrix address components
    uint32_t aThr = (uint32_t)((lane & 15) * 144 + ((lane >> 4) & 1) * 16);
    uint32_t bThr = (uint32_t)(((((lane >> 4) & 1) * 8 + (lane & 7)) * 584 +
                                ((lane >> 3) & 1) * 8) * 2 + n_idx * 37376);
    float bv[4][2];
#pragma unroll
    for (int j = 0; j < 4; j++) {
        bv[j][0] = sBias[n_idx * 32 + j * 8 + (lane & 3) * 2];
        bv[j][1] = sBias[n_idx * 32 + j * 8 + (lane & 3) * 2 + 1];
    }
    // A fragment row offsets: 4 m16 frags -> 2 image rows per warp
    uint32_t fragOff[4];
#pragma unroll
    for (int f = 0; f < 4; f++)
        fragOff[f] = (uint32_t)((2 * m_idx + (f >> 1)) * 4896 + (f & 1) * 16 * 144);

    for (int img = blockIdx.x; img < 1024; img += gridDim.x) {
        const uint32_t* gsrc = g_a32 + (size_t)img * 32768;
        float pool[4][2];
#pragma unroll
        for (int j = 0; j < 4; j++) { pool[j][0] = 0.f; pool[j][1] = 0.f; }

        for (int t = 0; t < 4; t++) {
            __syncthreads();  // previous tile's reads done before overwrite
            // load 10 rows (8 + 2 halo); grouped layout: 2560 chunks of 16B
#pragma unroll
            for (int i = 0; i < 5; i++) {
                int c = tid + i * 512;
                int wr = c >> 8, rem = c & 255;
                int px = rem >> 3, g = (rem >> 1) & 3, q = rem & 1;
                int gy = t * 8 + wr - 1;
                uint32_t ok = ((unsigned)gy < 32u) ? 16u : 0u;
                int gyc = gy < 0 ? 0 : (gy > 31 ? 31 : gy);
                const void* gp = gsrc + g * 8192 + (gyc * 32 + px) * 8 + q * 4;
                uint32_t sd = sbase + SIN_OFF +
                              (uint32_t)(wr * 4896 + (px + 1) * 144 + g * 32 + q * 16);
                asm volatile("cp.async.cg.shared.global [%0], [%1], 16, %2;"
                             :: "r"(sd), "l"(gp), "r"(ok) : "memory");
            }
            asm volatile("cp.async.commit_group;" ::: "memory");
            asm volatile("cp.async.wait_group 0;" ::: "memory");
            __syncthreads();

            float acc[4][4][4];
#pragma unroll
            for (int f = 0; f < 4; f++)
#pragma unroll
                for (int j = 0; j < 4; j++)
#pragma unroll
                    for (int q = 0; q < 4; q++) acc[f][j][q] = 0.f;

            uint32_t aBase = sbase + SIN_OFF + aThr;
            uint32_t bBase = sbase + B_OFF + bThr;
#pragma unroll
            for (int s = 0; s < 9; s++) {
                const uint32_t doff = (uint32_t)(((s / 3) * 34 + (s % 3)) * 144);
#pragma unroll
                for (int ks = 0; ks < 4; ks++) {
                    uint32_t a[4][4];
#pragma unroll
                    for (int f = 0; f < 4; f++)
                        ldmx4(a[f][0], a[f][1], a[f][2], a[f][3],
                              aBase + fragOff[f] + doff + ks * 32);
                    uint32_t kofs = (uint32_t)(s * 128 + ks * 32);
#pragma unroll
                    for (int fp = 0; fp < 2; fp++) {
                        uint32_t r0, r1, r2, r3;
                        ldmx4(r0, r1, r2, r3, bBase + (uint32_t)(fp * 18688) + kofs);
#pragma unroll
                        for (int f = 0; f < 4; f++) {
                            mma16816(acc[f][fp * 2], a[f], r0, r1);
                            mma16816(acc[f][fp * 2 + 1], a[f], r2, r3);
                        }
                    }
                }
            }
            // bias + relu + pixel-pool
#pragma unroll
            for (int f = 0; f < 4; f++)
#pragma unroll
                for (int j = 0; j < 4; j++) {
                    pool[j][0] += fmaxf(acc[f][j][0] + bv[j][0], 0.f) +
                                  fmaxf(acc[f][j][2] + bv[j][0], 0.f);
                    pool[j][1] += fmaxf(acc[f][j][1] + bv[j][1], 0.f) +
                                  fmaxf(acc[f][j][3] + bv[j][1], 0.f);
                }
        }
        // reduce over lanes with same (lane&3)
#pragma unroll
        for (int off = 4; off <= 16; off <<= 1)
#pragma unroll
            for (int j = 0; j < 4; j++) {
                pool[j][0] += __shfl_xor_sync(0xffffffffu, pool[j][0], off);
                pool[j][1] += __shfl_xor_sync(0xffffffffu, pool[j][1], off);
            }
        if (lane < 4) {
            float* sp = sPool + wid * 32;
#pragma unroll
            for (int j = 0; j < 4; j++) {
                sp[j * 8 + lane * 2] = pool[j][0];
                sp[j * 8 + lane * 2 + 1] = pool[j][1];
            }
        }
        __syncthreads();
        if (tid < 128) {
            int ni = tid >> 5, col = tid & 31;
            float s = 0.f;
#pragma unroll
            for (int m = 0; m < 4; m++) s += sPool[(ni * 4 + m) * 32 + col];
            g_pool[img * 128 + tid] = s * (1.f / 1024.f);
        }
    }
}

// ---------------- fused tail: fc + mask + colsum + sage1 + colsum + sage2 ----------------
static constexpr int TP_POOL = 0;       // 32 x 128
static constexpr int TP_H    = 4096;    // 32 x 256 (reused as sage2 partials)
static constexpr int TP_O1   = 12288;   // 32 x 256
static constexpr int TP_CS   = 20480;   // 256
static constexpr int TP_B2   = 20736;   // 256
static constexpr int TP_MASK = 20992;   // 32
static constexpr int TAIL_SMEM = 21024 * 4;

__global__ __launch_bounds__(256) void tail_kernel(
    const float* __restrict__ fc_w, const float* __restrict__ fc_b,
    const float* __restrict__ mask,
    const float* __restrict__ s1_lw, const float* __restrict__ s1_lb,
    const float* __restrict__ s1_rw,
    const float* __restrict__ s2_lw, const float* __restrict__ s2_lb,
    const float* __restrict__ s2_rw,
    float* __restrict__ out) {
    extern __shared__ float sm[];
    float* sPool = sm + TP_POOL;
    float* sH    = sm + TP_H;
    float* sO1   = sm + TP_O1;
    float* sCs   = sm + TP_CS;
    float* sB2   = sm + TP_B2;
    float* sMask = sm + TP_MASK;
    int b = blockIdx.x, tid = threadIdx.x;

    for (int e = tid; e < 4096; e += 256) sPool[e] = g_pool[b * 4096 + e];
    if (tid < 32) sMask[tid] = mask[b * 32 + tid];
    __syncthreads();

    // fc: thread = output dim o (256); 32 nodes in registers
    {
        float acc[32];
#pragma unroll
        for (int n = 0; n < 32; n++) acc[n] = 0.f;
        const float4* wrow = reinterpret_cast<const float4*>(fc_w + tid * 128);
#pragma unroll 4
        for (int k4 = 0; k4 < 32; k4++) {
            float4 wv = wrow[k4];
#pragma unroll
            for (int n = 0; n < 32; n++) {
                float4 hv = *reinterpret_cast<const float4*>(sPool + n * 128 + k4 * 4);
                acc[n] += wv.x * hv.x + wv.y * hv.y + wv.z * hv.z + wv.w * hv.w;
            }
        }
        float fb = fc_b[tid];
#pragma unroll
        for (int n = 0; n < 32; n++) sH[n * 256 + tid] = (acc[n] + fb) * sMask[n];
    }
    __syncthreads();
    {
        float s = 0.f;
#pragma unroll
        for (int n = 0; n < 32; n++) s += sH[n * 256 + tid];
        sCs[tid] = s;
    }
    __syncthreads();

    // sage1
    {
        float acc[32];
#pragma unroll
        for (int n = 0; n < 32; n++) acc[n] = 0.f;
        float bacc = 0.f;
        const float4* lw4 = reinterpret_cast<const float4*>(s1_lw + tid * 256);
        const float4* rw4 = reinterpret_cast<const float4*>(s1_rw + tid * 256);
#pragma unroll 2
        for (int k4 = 0; k4 < 64; k4++) {
            float4 lw = lw4[k4], rw = rw4[k4];
            float4 cs = *reinterpret_cast<const float4*>(sCs + k4 * 4);
            bacc += cs.x * lw.x + cs.y * lw.y + cs.z * lw.z + cs.w * lw.w;
            float4 wc;
            wc.x = rw.x - lw.x * (1.f / 31.f); wc.y = rw.y - lw.y * (1.f / 31.f);
            wc.z = rw.z - lw.z * (1.f / 31.f); wc.w = rw.w - lw.w * (1.f / 31.f);
#pragma unroll
            for (int n = 0; n < 32; n++) {
                float4 hv = *reinterpret_cast<const float4*>(sH + n * 256 + k4 * 4);
                acc[n] += wc.x * hv.x + wc.y * hv.y + wc.z * hv.z + wc.w * hv.w;
            }
        }
        float base = s1_lb[tid] + bacc * (1.f / 31.f);
#pragma unroll
        for (int n = 0; n < 32; n++) sO1[n * 256 + tid] = fmaxf(base + acc[n], 0.f);
    }
    __syncthreads();
    {
        float s = 0.f;
#pragma unroll
        for (int n = 0; n < 32; n++) s += sO1[n * 256 + tid];
        sCs[tid] = s;
    }
    __syncthreads();

    // sage2: o2 = tid&127, k-half = tid>>7
    {
        int o2 = tid & 127, half = tid >> 7;
        float acc[32];
#pragma unroll
        for (int n = 0; n < 32; n++) acc[n] = 0.f;
        float bacc = 0.f;
        const float4* lw4 = reinterpret_cast<const float4*>(s2_lw + o2 * 256 + half * 128);
        const float4* rw4 = reinterpret_cast<const float4*>(s2_rw + o2 * 256 + half * 128);
        const float* csb = sCs + half * 128;
        const float* o1b = sO1 + half * 128;
#pragma unroll 2
        for (int k4 = 0; k4 < 32; k4++) {
            float4 lw = lw4[k4], rw = rw4[k4];
            float4 cs = *reinterpret_cast<const float4*>(csb + k4 * 4);
            bacc += cs.x * lw.x + cs.y * lw.y + cs.z * lw.z + cs.w * lw.w;
            float4 wc;
            wc.x = rw.x - lw.x * (1.f / 31.f); wc.y = rw.y - lw.y * (1.f / 31.f);
            wc.z = rw.z - lw.z * (1.f / 31.f); wc.w = rw.w - lw.w * (1.f / 31.f);
#pragma unroll
            for (int n = 0; n < 32; n++) {
                float4 hv = *reinterpret_cast<const float4*>(o1b + n * 256 + k4 * 4);
                acc[n] += wc.x * hv.x + wc.y * hv.y + wc.z * hv.z + wc.w * hv.w;
            }
        }
#pragma unroll
        for (int n = 0; n < 32; n++) sH[n * 256 + tid] = acc[n];
        sB2[tid] = bacc;
    }
    __syncthreads();
    for (int e = tid; e < 4096; e += 256) {
        int n = e >> 7, o2 = e & 127;
        float v = sH[n * 256 + o2] + sH[n * 256 + o2 + 128];
        float base = s2_lb[o2] + (sB2[o2] + sB2[o2 + 128]) * (1.f / 31.f);
        out[(b * 32 + n) * 128 + o2] = base + v;
    }
}

// ---------------- launch ----------------
extern "C" void kernel_launch(void* const* d_in, const int* in_sizes, int n_in,
                              void* d_out, int out_size) {
    const float* x       = (const float*)d_in[0];
    const float* mask    = (const float*)d_in[1];
    const float* conv1_w = (const float*)d_in[2];
    const float* conv1_b = (const float*)d_in[3];
    const float* conv2_w = (const float*)d_in[4];
    const float* conv2_b = (const float*)d_in[5];
    const float* fc_w    = (const float*)d_in[6];
    const float* fc_b    = (const float*)d_in[7];
    const float* s1_lw   = (const float*)d_in[8];
    const float* s1_lb   = (const float*)d_in[9];
    const float* s1_rw   = (const float*)d_in[10];
    const float* s2_lw   = (const float*)d_in[11];
    const float* s2_lb   = (const float*)d_in[12];
    const float* s2_rw   = (const float*)d_in[13];
    float* out = (float*)d_out;

    cudaFuncSetAttribute(conv1_kernel, cudaFuncAttributeMaxDynamicSharedMemorySize, C1_SMEM);
    cudaFuncSetAttribute(conv2_mma_kernel, cudaFuncAttributeMaxDynamicSharedMemorySize,
                         SMEM2_TOTAL);
    cudaFuncSetAttribute(tail_kernel, cudaFuncAttributeMaxDynamicSharedMemorySize, TAIL_SMEM);

    conv1_kernel<<<1024, 256, C1_SMEM>>>(x, conv1_w, conv1_b);
    conv2_mma_kernel<<<148, 512, SMEM2_TOTAL>>>(conv2_w, conv2_b);
    tail_kernel<<<32, 256, TAIL_SMEM>>>(fc_w, fc_b, mask, s1_lw, s1_lb, s1_rw,
                                        s2_lw, s2_lb, s2_rw, out);
}

// round 10
// speedup vs baseline: 1.3194x; 1.0659x over previous
#include <cuda_runtime.h>
#include <cuda_fp16.h>
#include <cstdint>

typedef unsigned long long ull;

// ---------------- scratch (__device__ globals; no allocation) ----------------
// layout: [img][ocGroup 0..3][px 0..1023][8 words of 16 fp16 ch]
__device__ uint32_t g_a32[1024 * 32768];   // conv1 output (134MB)
__device__ float g_pool[1024 * 128];       // pooled conv2 features

// ---------------- helpers ----------------
__device__ __forceinline__ uint32_t smem_u32(const void* p) {
    uint32_t a;
    asm("{ .reg .u64 t; cvta.to.shared.u64 t, %1; cvt.u32.u64 %0, t; }" : "=r"(a) : "l"(p));
    return a;
}
__device__ __forceinline__ uint32_t pack_h2(float a, float b) {
    __half2 t = __floats2half2_rn(a, b);
    return *reinterpret_cast<uint32_t*>(&t);
}
__device__ __forceinline__ ull pk2(float v) {
    ull r; asm("mov.b64 %0, {%1, %2};" : "=l"(r) : "f"(v), "f"(v)); return r;
}
__device__ __forceinline__ ull ffma2(ull a, ull b, ull c) {
    ull d; asm("fma.rn.f32x2 %0, %1, %2, %3;" : "=l"(d) : "l"(a), "l"(b), "l"(c)); return d;
}
__device__ __forceinline__ float2 upk(ull v) {
    float2 f; asm("mov.b64 {%0, %1}, %2;" : "=f"(f.x), "=f"(f.y) : "l"(v)); return f;
}
__device__ __forceinline__ void ldmx4(uint32_t& r0, uint32_t& r1, uint32_t& r2, uint32_t& r3,
                                      uint32_t addr) {
    asm volatile("ldmatrix.sync.aligned.m8n8.x4.shared.b16 {%0,%1,%2,%3}, [%4];"
                 : "=r"(r0), "=r"(r1), "=r"(r2), "=r"(r3) : "r"(addr));
}
__device__ __forceinline__ void mma16816(float* c, const uint32_t* a, uint32_t b0, uint32_t b1) {
    asm volatile(
        "mma.sync.aligned.m16n8k16.row.col.f32.f16.f16.f32 "
        "{%0,%1,%2,%3}, {%4,%5,%6,%7}, {%8,%9}, {%0,%1,%2,%3};"
        : "+f"(c[0]), "+f"(c[1]), "+f"(c[2]), "+f"(c[3])
        : "r"(a[0]), "r"(a[1]), "r"(a[2]), "r"(a[3]), "r"(b0), "r"(b1));
}

// ---------------- conv1 (3->64, 3x3 SAME) + ReLU -> grouped NHWC fp16 ----------------
// FFMA2 packed over oc pairs. dynamic smem: sIn 3072f | sW 1728f | sB 64f | stage 9216w
static constexpr int C1_SMEM = 56320;

__global__ __launch_bounds__(256) void conv1_kernel(const float* __restrict__ x,
                                                    const float* __restrict__ w,
                                                    const float* __restrict__ bias) {
    extern __shared__ float c1s[];
    float* sIn = c1s;                  // 3072
    float* sW  = c1s + 3072;           // 1728  [kt][oc]
    float* sB  = c1s + 4800;           // 64
    uint32_t* stage = reinterpret_cast<uint32_t*>(c1s + 4864);  // 1024 px * 9 words

    int img = blockIdx.x, tid = threadIdx.x;
    for (int j = tid; j < 3072; j += 256) sIn[j] = x[img * 3072 + j];
    for (int e = tid; e < 1728; e += 256) { int k = e >> 6, o = e & 63; sW[e] = w[o * 27 + k]; }
    if (tid < 64) sB[tid] = bias[tid];
    __syncthreads();
    int r = tid >> 3, x0 = (tid & 7) << 2;

    for (int oc0 = 0; oc0 < 64; oc0 += 16) {
        ull acc2[4][8];
        {
            const ull* b2 = reinterpret_cast<const ull*>(sB + oc0);
#pragma unroll
            for (int p = 0; p < 4; p++)
#pragma unroll
                for (int j = 0; j < 8; j++) acc2[p][j] = b2[j];
        }
#pragma unroll
        for (int ic = 0; ic < 3; ic++) {
#pragma unroll
            for (int ky = 0; ky < 3; ky++) {
                int yy = r + ky - 1;
                ull iv2[6];
                if ((unsigned)yy < 32u) {
                    const float* row = sIn + ic * 1024 + yy * 32;
#pragma unroll
                    for (int j = 0; j < 6; j++) {
                        int xx = x0 - 1 + j;
                        iv2[j] = pk2(((unsigned)xx < 32u) ? row[xx] : 0.f);
                    }
                } else {
#pragma unroll
                    for (int j = 0; j < 6; j++) iv2[j] = pk2(0.f);
                }
#pragma unroll
                for (int kx = 0; kx < 3; kx++) {
                    const ull* wp2 = reinterpret_cast<const ull*>(
                        sW + (ic * 9 + ky * 3 + kx) * 64 + oc0);
                    ull w2[8];
#pragma unroll
                    for (int j = 0; j < 8; j++) w2[j] = wp2[j];
#pragma unroll
                    for (int p = 0; p < 4; p++) {
                        ull v = iv2[p + kx];
#pragma unroll
                        for (int j = 0; j < 8; j++) acc2[p][j] = ffma2(v, w2[j], acc2[p][j]);
                    }
                }
            }
        }
        // stage (XOR-swizzled, conflict-free) then flush coalesced
        __syncthreads();   // previous group's flush readers done
#pragma unroll
        for (int p = 0; p < 4; p++) {
            int pix = r * 32 + x0 + p;
            int xr = (pix >> 5) & 7;
            uint32_t* st = stage + pix * 9;
#pragma unroll
            for (int j = 0; j < 8; j++) {
                float2 f = upk(acc2[p][j]);
                st[j ^ xr] = pack_h2(fmaxf(f.x, 0.f), fmaxf(f.y, 0.f));
            }
        }
        __syncthreads();
        {
            int g = oc0 >> 4;
            uint4* dst = reinterpret_cast<uint4*>(g_a32 + (size_t)img * 32768 + g * 8192);
            int px0 = tid >> 1, w0 = (tid & 1) * 4;
#pragma unroll
            for (int k4 = 0; k4 < 8; k4++) {
                int px = px0 + k4 * 128;
                int xr = (px >> 5) & 7;
                const uint32_t* st = stage + px * 9;
                uint4 v;
                v.x = st[(w0 + 0) ^ xr];
                v.y = st[(w0 + 1) ^ xr];
                v.z = st[(w0 + 2) ^ xr];
                v.w = st[(w0 + 3) ^ xr];
                dst[tid + k4 * 256] = v;
            }
        }
    }
}

// ---------------- conv2 via mma.sync fp16, ping-pong A buffers + ReLU + pool ----------
// SMEM: B 149504 | 2 x A buf (6 rows x 34 px x 144B = 29376) | bias 512 | pool 2048
static constexpr int B_OFF = 0;
static constexpr int ABUF_OFF = 149504;
static constexpr int ABUF_SZ = 29376;
static constexpr int SBIAS_OFF = 208256;
static constexpr int SPOOL_OFF = 208768;
static constexpr int SMEM2_TOTAL = 210816;

// load 6 rows (4 + 2 halo) of tile t into buffer b
__device__ __forceinline__ void c2_load_tile(uint32_t sbase, const uint32_t* gsrc,
                                             int t, int b, int tid) {
#pragma unroll
    for (int i = 0; i < 3; i++) {
        int c = tid + i * 512;
        int wr = c >> 8, rem = c & 255;
        int px = rem >> 3, g = (rem >> 1) & 3, q = rem & 1;
        int gy = t * 4 + wr - 1;
        uint32_t ok = ((unsigned)gy < 32u) ? 16u : 0u;
        int gyc = gy < 0 ? 0 : (gy > 31 ? 31 : gy);
        const void* gp = gsrc + g * 8192 + (gyc * 32 + px) * 8 + q * 4;
        uint32_t sd = sbase + ABUF_OFF + (uint32_t)(b * ABUF_SZ) +
                      (uint32_t)(wr * 4896 + (px + 1) * 144 + g * 32 + q * 16);
        asm volatile("cp.async.cg.shared.global [%0], [%1], 16, %2;"
                     :: "r"(sd), "l"(gp), "r"(ok) : "memory");
    }
}

__global__ __launch_bounds__(512, 1) void conv2_mma_kernel(const float* __restrict__ w,
                                                           const float* __restrict__ bias) {
    extern __shared__ __align__(16) char smem[];
    uint32_t sbase = smem_u32(smem);
    float* sBias = reinterpret_cast<float*>(smem + SBIAS_OFF);
    float* sPool = reinterpret_cast<float*>(smem + SPOOL_OFF);
    int tid = threadIdx.x, lane = tid & 31, wid = tid >> 5;
    int m_idx = wid & 3, n_idx = wid >> 2;   // 4 m-warps (32px row each) x 4 n-warps (32oc)

    // zero x-halo pixels (px cols 0, 33) of both buffers, 6 rows each
    for (int e = tid; e < 864; e += 512) {
        int b = e / 432, rem = e % 432;
        int rr = rem / 72, rem2 = rem % 72;
        int side = rem2 / 36, q = rem2 % 36;
        *reinterpret_cast<uint32_t*>(smem + ABUF_OFF + b * ABUF_SZ + rr * 4896 +
                                     (side ? 33 : 0) * 144 + q * 4) = 0u;
    }
    // build B: sB[n][k], k = s*64 + ic, k-stride padded to 584 elems (fp16)
    for (int e = tid; e < 73728; e += 512) {
        int n = e / 576, k = e - n * 576;
        int ic = k & 63, s = k >> 6;
        float v = w[n * 576 + ic * 9 + s];
        *reinterpret_cast<__half*>(smem + B_OFF + (n * 584 + k) * 2) = __float2half(v);
    }
    if (tid < 128) sBias[tid] = bias[tid];
    __syncthreads();

    // per-thread ldmatrix address components
    uint32_t aThr = (uint32_t)((lane & 15) * 144 + ((lane >> 4) & 1) * 16);
    uint32_t bThr = (uint32_t)(((((lane >> 4) & 1) * 8 + (lane & 7)) * 584 +
                                ((lane >> 3) & 1) * 8) * 2 + n_idx * 37376);
    float bv[4][2];
#pragma unroll
    for (int j = 0; j < 4; j++) {
        bv[j][0] = sBias[n_idx * 32 + j * 8 + (lane & 3) * 2];
        bv[j][1] = sBias[n_idx * 32 + j * 8 + (lane & 3) * 2 + 1];
    }

    for (int img = blockIdx.x; img < 1024; img += gridDim.x) {
        const uint32_t* gsrc = g_a32 + (size_t)img * 32768;
        float pool[4][2];
#pragma unroll
        for (int j = 0; j < 4; j++) { pool[j][0] = 0.f; pool[j][1] = 0.f; }

        c2_load_tile(sbase, gsrc, 0, 0, tid);
        asm volatile("cp.async.commit_group;" ::: "memory");

        for (int t = 0; t < 8; t++) {
            asm volatile("cp.async.wait_group 0;" ::: "memory");
            __syncthreads();          // data visible; all compute(t-1) done
            if (t < 7) {
                c2_load_tile(sbase, gsrc, t + 1, (t + 1) & 1, tid);  // overlaps compute
                asm volatile("cp.async.commit_group;" ::: "memory");
            }

            float acc[2][4][4];
#pragma unroll
            for (int f = 0; f < 2; f++)
#pragma unroll
                for (int j = 0; j < 4; j++)
#pragma unroll
                    for (int q = 0; q < 4; q++) acc[f][j][q] = 0.f;

            uint32_t aBase = sbase + ABUF_OFF + (uint32_t)((t & 1) * ABUF_SZ) +
                             (uint32_t)(m_idx * 4896) + aThr;
            uint32_t bBase = sbase + B_OFF + bThr;
#pragma unroll
            for (int s = 0; s < 9; s++) {
                const uint32_t doff = (uint32_t)((s / 3) * 4896 + (s % 3) * 144);
#pragma unroll
                for (int ks = 0; ks < 4; ks++) {
                    uint32_t a[2][4];
#pragma unroll
                    for (int f = 0; f < 2; f++)
                        ldmx4(a[f][0], a[f][1], a[f][2], a[f][3],
                              aBase + doff + (uint32_t)(f * 2304 + ks * 32));
                    uint32_t kofs = (uint32_t)(s * 128 + ks * 32);
#pragma unroll
                    for (int fp = 0; fp < 2; fp++) {
                        uint32_t r0, r1, r2, r3;
                        ldmx4(r0, r1, r2, r3, bBase + (uint32_t)(fp * 18688) + kofs);
#pragma unroll
                        for (int f = 0; f < 2; f++) {
                            mma16816(acc[f][fp * 2], a[f], r0, r1);
                            mma16816(acc[f][fp * 2 + 1], a[f], r2, r3);
                        }
                    }
                }
            }
            // bias + relu + pixel-pool
#pragma unroll
            for (int f = 0; f < 2; f++)
#pragma unroll
                for (int j = 0; j < 4; j++) {
                    pool[j][0] += fmaxf(acc[f][j][0] + bv[j][0], 0.f) +
                                  fmaxf(acc[f][j][2] + bv[j][0], 0.f);
                    pool[j][1] += fmaxf(acc[f][j][1] + bv[j][1], 0.f) +
                                  fmaxf(acc[f][j][3] + bv[j][1], 0.f);
                }
        }
        // reduce over lanes with same (lane&3)
#pragma unroll
        for (int off = 4; off <= 16; off <<= 1)
#pragma unroll
            for (int j = 0; j < 4; j++) {
                pool[j][0] += __shfl_xor_sync(0xffffffffu, pool[j][0], off);
                pool[j][1] += __shfl_xor_sync(0xffffffffu, pool[j][1], off);
            }
        if (lane < 4) {
            float* sp = sPool + wid * 32;
#pragma unroll
            for (int j = 0; j < 4; j++) {
                sp[j * 8 + lane * 2] = pool[j][0];
                sp[j * 8 + lane * 2 + 1] = pool[j][1];
            }
        }
        __syncthreads();
        if (tid < 128) {
            int ni = tid >> 5, col = tid & 31;
            float s = 0.f;
#pragma unroll
            for (int m = 0; m < 4; m++) s += sPool[(ni * 4 + m) * 32 + col];
            g_pool[img * 128 + tid] = s * (1.f / 1024.f);
        }
    }
}

// ---------------- fused tail: fc + mask + colsum + sage1 + colsum + sage2 ----------------
static constexpr int TP_POOL = 0;       // 32 x 128
static constexpr int TP_H    = 4096;    // 32 x 256 (reused as sage2 partials)
static constexpr int TP_O1   = 12288;   // 32 x 256
static constexpr int TP_CS   = 20480;   // 256
static constexpr int TP_B2   = 20736;   // 256
static constexpr int TP_MASK = 20992;   // 32
static constexpr int TAIL_SMEM = 21024 * 4;

__global__ __launch_bounds__(256) void tail_kernel(
    const float* __restrict__ fc_w, const float* __restrict__ fc_b,
    const float* __restrict__ mask,
    const float* __restrict__ s1_lw, const float* __restrict__ s1_lb,
    const float* __restrict__ s1_rw,
    const float* __restrict__ s2_lw, const float* __restrict__ s2_lb,
    const float* __restrict__ s2_rw,
    float* __restrict__ out) {
    extern __shared__ float sm[];
    float* sPool = sm + TP_POOL;
    float* sH    = sm + TP_H;
    float* sO1   = sm + TP_O1;
    float* sCs   = sm + TP_CS;
    float* sB2   = sm + TP_B2;
    float* sMask = sm + TP_MASK;
    int b = blockIdx.x, tid = threadIdx.x;

    for (int e = tid; e < 4096; e += 256) sPool[e] = g_pool[b * 4096 + e];
    if (tid < 32) sMask[tid] = mask[b * 32 + tid];
    __syncthreads();

    // fc: thread = output dim o (256); 32 nodes in registers
    {
        float acc[32];
#pragma unroll
        for (int n = 0; n < 32; n++) acc[n] = 0.f;
        const float4* wrow = reinterpret_cast<const float4*>(fc_w + tid * 128);
#pragma unroll 4
        for (int k4 = 0; k4 < 32; k4++) {
            float4 wv = wrow[k4];
#pragma unroll
            for (int n = 0; n < 32; n++) {
                float4 hv = *reinterpret_cast<const float4*>(sPool + n * 128 + k4 * 4);
                acc[n] += wv.x * hv.x + wv.y * hv.y + wv.z * hv.z + wv.w * hv.w;
            }
        }
        float fb = fc_b[tid];
#pragma unroll
        for (int n = 0; n < 32; n++) sH[n * 256 + tid] = (acc[n] + fb) * sMask[n];
    }
    __syncthreads();
    {
        float s = 0.f;
#pragma unroll
        for (int n = 0; n < 32; n++) s += sH[n * 256 + tid];
        sCs[tid] = s;
    }
    __syncthreads();

    // sage1
    {
        float acc[32];
#pragma unroll
        for (int n = 0; n < 32; n++) acc[n] = 0.f;
        float bacc = 0.f;
        const float4* lw4 = reinterpret_cast<const float4*>(s1_lw + tid * 256);
        const float4* rw4 = reinterpret_cast<const float4*>(s1_rw + tid * 256);
#pragma unroll 2
        for (int k4 = 0; k4 < 64; k4++) {
            float4 lw = lw4[k4], rw = rw4[k4];
            float4 cs = *reinterpret_cast<const float4*>(sCs + k4 * 4);
            bacc += cs.x * lw.x + cs.y * lw.y + cs.z * lw.z + cs.w * lw.w;
            float4 wc;
            wc.x = rw.x - lw.x * (1.f / 31.f); wc.y = rw.y - lw.y * (1.f / 31.f);
            wc.z = rw.z - lw.z * (1.f / 31.f); wc.w = rw.w - lw.w * (1.f / 31.f);
#pragma unroll
            for (int n = 0; n < 32; n++) {
                float4 hv = *reinterpret_cast<const float4*>(sH + n * 256 + k4 * 4);
                acc[n] += wc.x * hv.x + wc.y * hv.y + wc.z * hv.z + wc.w * hv.w;
            }
        }
        float base = s1_lb[tid] + bacc * (1.f / 31.f);
#pragma unroll
        for (int n = 0; n < 32; n++) sO1[n * 256 + tid] = fmaxf(base + acc[n], 0.f);
    }
    __syncthreads();
    {
        float s = 0.f;
#pragma unroll
        for (int n = 0; n < 32; n++) s += sO1[n * 256 + tid];
        sCs[tid] = s;
    }
    __syncthreads();

    // sage2: o2 = tid&127, k-half = tid>>7
    {
        int o2 = tid & 127, half = tid >> 7;
        float acc[32];
#pragma unroll
        for (int n = 0; n < 32; n++) acc[n] = 0.f;
        float bacc = 0.f;
        const float4* lw4 = reinterpret_cast<const float4*>(s2_lw + o2 * 256 + half * 128);
        const float4* rw4 = reinterpret_cast<const float4*>(s2_rw + o2 * 256 + half * 128);
        const float* csb = sCs + half * 128;
        const float* o1b = sO1 + half * 128;
#pragma unroll 2
        for (int k4 = 0; k4 < 32; k4++) {
            float4 lw = lw4[k4], rw = rw4[k4];
            float4 cs = *reinterpret_cast<const float4*>(csb + k4 * 4);
            bacc += cs.x * lw.x + cs.y * lw.y + cs.z * lw.z + cs.w * lw.w;
            float4 wc;
            wc.x = rw.x - lw.x * (1.f / 31.f); wc.y = rw.y - lw.y * (1.f / 31.f);
            wc.z = rw.z - lw.z * (1.f / 31.f); wc.w = rw.w - lw.w * (1.f / 31.f);
#pragma unroll
            for (int n = 0; n < 32; n++) {
                float4 hv = *reinterpret_cast<const float4*>(o1b + n * 256 + k4 * 4);
                acc[n] += wc.x * hv.x + wc.y * hv.y + wc.z * hv.z + wc.w * hv.w;
            }
        }
#pragma unroll
        for (int n = 0; n < 32; n++) sH[n * 256 + tid] = acc[n];
        sB2[tid] = bacc;
    }
    __syncthreads();
    for (int e = tid; e < 4096; e += 256) {
        int n = e >> 7, o2 = e & 127;
        float v = sH[n * 256 + o2] + sH[n * 256 + o2 + 128];
        float base = s2_lb[o2] + (sB2[o2] + sB2[o2 + 128]) * (1.f / 31.f);
        out[(b * 32 + n) * 128 + o2] = base + v;
    }
}

// ---------------- launch ----------------
extern "C" void kernel_launch(void* const* d_in, const int* in_sizes, int n_in,
                              void* d_out, int out_size) {
    const float* x       = (const float*)d_in[0];
    const float* mask    = (const float*)d_in[1];
    const float* conv1_w = (const float*)d_in[2];
    const float* conv1_b = (const float*)d_in[3];
    const float* conv2_w = (const float*)d_in[4];
    const float* conv2_b = (const float*)d_in[5];
    const float* fc_w    = (const float*)d_in[6];
    const float* fc_b    = (const float*)d_in[7];
    const float* s1_lw   = (const float*)d_in[8];
    const float* s1_lb   = (const float*)d_in[9];
    const float* s1_rw   = (const float*)d_in[10];
    const float* s2_lw   = (const float*)d_in[11];
    const float* s2_lb   = (const float*)d_in[12];
    const float* s2_rw   = (const float*)d_in[13];
    float* out = (float*)d_out;

    cudaFuncSetAttribute(conv1_kernel, cudaFuncAttributeMaxDynamicSharedMemorySize, C1_SMEM);
    cudaFuncSetAttribute(conv2_mma_kernel, cudaFuncAttributeMaxDynamicSharedMemorySize,
                         SMEM2_TOTAL);
    cudaFuncSetAttribute(tail_kernel, cudaFuncAttributeMaxDynamicSharedMemorySize, TAIL_SMEM);

    conv1_kernel<<<1024, 256, C1_SMEM>>>(x, conv1_w, conv1_b);
    conv2_mma_kernel<<<148, 512, SMEM2_TOTAL>>>(conv2_w, conv2_b);
    tail_kernel<<<32, 256, TAIL_SMEM>>>(fc_w, fc_b, mask, s1_lw, s1_lb, s1_rw,
                                        s2_lw, s2_lb, s2_rw, out);
}

// round 11
// speedup vs baseline: 1.3547x; 1.0268x over previous
#include <cuda_runtime.h>
#include <cuda_fp16.h>
#include <cstdint>

typedef unsigned long long ull;

// ---------------- scratch (__device__ globals; no allocation) ----------------
// layout: [img][ocGroup 0..3][px 0..1023][8 words of 16 fp16 ch]
__device__ uint32_t g_a32[1024 * 32768];   // conv1 output (134MB)
__device__ float g_pool[1024 * 128];       // pooled conv2 features

// ---------------- helpers ----------------
__device__ __forceinline__ uint32_t smem_u32(const void* p) {
    uint32_t a;
    asm("{ .reg .u64 t; cvta.to.shared.u64 t, %1; cvt.u32.u64 %0, t; }" : "=r"(a) : "l"(p));
    return a;
}
__device__ __forceinline__ uint32_t pack_h2(float a, float b) {
    __half2 t = __floats2half2_rn(a, b);
    return *reinterpret_cast<uint32_t*>(&t);
}
__device__ __forceinline__ ull pk2(float v) {
    ull r; asm("mov.b64 %0, {%1, %2};" : "=l"(r) : "f"(v), "f"(v)); return r;
}
__device__ __forceinline__ ull ffma2(ull a, ull b, ull c) {
    ull d; asm("fma.rn.f32x2 %0, %1, %2, %3;" : "=l"(d) : "l"(a), "l"(b), "l"(c)); return d;
}
__device__ __forceinline__ float2 upk(ull v) {
    float2 f; asm("mov.b64 {%0, %1}, %2;" : "=f"(f.x), "=f"(f.y) : "l"(v)); return f;
}
__device__ __forceinline__ void ldmx4(uint32_t& r0, uint32_t& r1, uint32_t& r2, uint32_t& r3,
                                      uint32_t addr) {
    asm volatile("ldmatrix.sync.aligned.m8n8.x4.shared.b16 {%0,%1,%2,%3}, [%4];"
                 : "=r"(r0), "=r"(r1), "=r"(r2), "=r"(r3) : "r"(addr));
}
__device__ __forceinline__ void mma16816(float* c, const uint32_t* a, uint32_t b0, uint32_t b1) {
    asm volatile(
        "mma.sync.aligned.m16n8k16.row.col.f32.f16.f16.f32 "
        "{%0,%1,%2,%3}, {%4,%5,%6,%7}, {%8,%9}, {%0,%1,%2,%3};"
        : "+f"(c[0]), "+f"(c[1]), "+f"(c[2]), "+f"(c[3])
        : "r"(a[0]), "r"(a[1]), "r"(a[2]), "r"(a[3]), "r"(b0), "r"(b1));
}

// ---------------- conv1 (3->64, 3x3 SAME) + ReLU -> grouped NHWC fp16 ----------------
// FFMA2, 2 px/thread, 512 threads/block (low reg pressure, high occupancy).
// dynamic smem: sIn 3072f | sW 1728f | sB 64f | stage 9216w = 56320 bytes
static constexpr int C1_SMEM = 56320;

__global__ __launch_bounds__(512) void conv1_kernel(const float* __restrict__ x,
                                                    const float* __restrict__ w,
                                                    const float* __restrict__ bias) {
    extern __shared__ float c1s[];
    float* sIn = c1s;                  // 3072
    float* sW  = c1s + 3072;           // 1728  [kt][oc]
    float* sB  = c1s + 4800;           // 64
    uint32_t* stage = reinterpret_cast<uint32_t*>(c1s + 4864);  // 1024 px * 9 words

    int img = blockIdx.x, tid = threadIdx.x;
    for (int j = tid; j < 3072; j += 512) sIn[j] = x[img * 3072 + j];
    for (int e = tid; e < 1728; e += 512) { int k = e >> 6, o = e & 63; sW[e] = w[o * 27 + k]; }
    if (tid < 64) sB[tid] = bias[tid];
    __syncthreads();
    int r = tid >> 4, x0 = (tid & 15) << 1;   // row 0..31, col pair base

    for (int oc0 = 0; oc0 < 64; oc0 += 16) {
        ull acc2[2][8];
        {
            const ull* b2 = reinterpret_cast<const ull*>(sB + oc0);
#pragma unroll
            for (int p = 0; p < 2; p++)
#pragma unroll
                for (int j = 0; j < 8; j++) acc2[p][j] = b2[j];
        }
#pragma unroll
        for (int ic = 0; ic < 3; ic++) {
#pragma unroll
            for (int ky = 0; ky < 3; ky++) {
                int yy = r + ky - 1;
                ull iv2[4];
                if ((unsigned)yy < 32u) {
                    const float* row = sIn + ic * 1024 + yy * 32;
#pragma unroll
                    for (int j = 0; j < 4; j++) {
                        int xx = x0 - 1 + j;
                        iv2[j] = pk2(((unsigned)xx < 32u) ? row[xx] : 0.f);
                    }
                } else {
#pragma unroll
                    for (int j = 0; j < 4; j++) iv2[j] = pk2(0.f);
                }
#pragma unroll
                for (int kx = 0; kx < 3; kx++) {
                    const ull* wp2 = reinterpret_cast<const ull*>(
                        sW + (ic * 9 + ky * 3 + kx) * 64 + oc0);
                    ull w2[8];
#pragma unroll
                    for (int j = 0; j < 8; j++) w2[j] = wp2[j];
#pragma unroll
                    for (int p = 0; p < 2; p++) {
                        ull v = iv2[p + kx];
#pragma unroll
                        for (int j = 0; j < 8; j++) acc2[p][j] = ffma2(v, w2[j], acc2[p][j]);
                    }
                }
            }
        }
        // stage (XOR-swizzled, conflict-free) then flush coalesced
        __syncthreads();   // previous group's flush readers done
#pragma unroll
        for (int p = 0; p < 2; p++) {
            int pix = r * 32 + x0 + p;
            int xr = (pix >> 5) & 7;
            uint32_t* st = stage + pix * 9;
#pragma unroll
            for (int j = 0; j < 8; j++) {
                float2 f = upk(acc2[p][j]);
                st[j ^ xr] = pack_h2(fmaxf(f.x, 0.f), fmaxf(f.y, 0.f));
            }
        }
        __syncthreads();
        {
            int g = oc0 >> 4;
            uint4* dst = reinterpret_cast<uint4*>(g_a32 + (size_t)img * 32768 + g * 8192);
            int px0 = tid >> 1, w0 = (tid & 1) * 4;
#pragma unroll
            for (int k4 = 0; k4 < 4; k4++) {
                int px = px0 + k4 * 256;
                int xr = (px >> 5) & 7;
                const uint32_t* st = stage + px * 9;
                uint4 v;
                v.x = st[(w0 + 0) ^ xr];
                v.y = st[(w0 + 1) ^ xr];
                v.z = st[(w0 + 2) ^ xr];
                v.w = st[(w0 + 3) ^ xr];
                dst[tid + k4 * 512] = v;
            }
        }
    }
}

// ---------------- conv2 via mma.sync fp16, ping-pong A buffers + ReLU + pool ----------
// SMEM: B 149504 | 2 x A buf (6 rows x 34 px x 144B = 29376) | bias 512 | pool 2048
static constexpr int B_OFF = 0;
static constexpr int ABUF_OFF = 149504;
static constexpr int ABUF_SZ = 29376;
static constexpr int SBIAS_OFF = 208256;
static constexpr int SPOOL_OFF = 208768;
static constexpr int SMEM2_TOTAL = 210816;

// load 6 rows (4 + 2 halo) of tile t into buffer b
__device__ __forceinline__ void c2_load_tile(uint32_t sbase, const uint32_t* gsrc,
                                             int t, int b, int tid) {
#pragma unroll
    for (int i = 0; i < 3; i++) {
        int c = tid + i * 512;
        int wr = c >> 8, rem = c & 255;
        int px = rem >> 3, g = (rem >> 1) & 3, q = rem & 1;
        int gy = t * 4 + wr - 1;
        uint32_t ok = ((unsigned)gy < 32u) ? 16u : 0u;
        int gyc = gy < 0 ? 0 : (gy > 31 ? 31 : gy);
        const void* gp = gsrc + g * 8192 + (gyc * 32 + px) * 8 + q * 4;
        uint32_t sd = sbase + ABUF_OFF + (uint32_t)(b * ABUF_SZ) +
                      (uint32_t)(wr * 4896 + (px + 1) * 144 + g * 32 + q * 16);
        asm volatile("cp.async.cg.shared.global [%0], [%1], 16, %2;"
                     :: "r"(sd), "l"(gp), "r"(ok) : "memory");
    }
}

__global__ __launch_bounds__(512, 1) void conv2_mma_kernel(const float* __restrict__ w,
                                                           const float* __restrict__ bias) {
    extern __shared__ __align__(16) char smem[];
    uint32_t sbase = smem_u32(smem);
    float* sBias = reinterpret_cast<float*>(smem + SBIAS_OFF);
    float* sPool = reinterpret_cast<float*>(smem + SPOOL_OFF);
    int tid = threadIdx.x, lane = tid & 31, wid = tid >> 5;
    int m_idx = wid & 3, n_idx = wid >> 2;   // 4 m-warps (32px row each) x 4 n-warps (32oc)

    // zero x-halo pixels (px cols 0, 33) of both buffers, 6 rows each
    for (int e = tid; e < 864; e += 512) {
        int b = e / 432, rem = e % 432;
        int rr = rem / 72, rem2 = rem % 72;
        int side = rem2 / 36, q = rem2 % 36;
        *reinterpret_cast<uint32_t*>(smem + ABUF_OFF + b * ABUF_SZ + rr * 4896 +
                                     (side ? 33 : 0) * 144 + q * 4) = 0u;
    }
    // build B: sB[n][k], k = s*64 + ic, k-stride padded to 584 elems (fp16)
    for (int e = tid; e < 73728; e += 512) {
        int n = e / 576, k = e - n * 576;
        int ic = k & 63, s = k >> 6;
        float v = w[n * 576 + ic * 9 + s];
        *reinterpret_cast<__half*>(smem + B_OFF + (n * 584 + k) * 2) = __float2half(v);
    }
    if (tid < 128) sBias[tid] = bias[tid];
    __syncthreads();

    // per-thread ldmatrix address components
    uint32_t aThr = (uint32_t)((lane & 15) * 144 + ((lane >> 4) & 1) * 16);
    uint32_t bThr = (uint32_t)(((((lane >> 4) & 1) * 8 + (lane & 7)) * 584 +
                                ((lane >> 3) & 1) * 8) * 2 + n_idx * 37376);
    float bv[4][2];
#pragma unroll
    for (int j = 0; j < 4; j++) {
        bv[j][0] = sBias[n_idx * 32 + j * 8 + (lane & 3) * 2];
        bv[j][1] = sBias[n_idx * 32 + j * 8 + (lane & 3) * 2 + 1];
    }

    for (int img = blockIdx.x; img < 1024; img += gridDim.x) {
        const uint32_t* gsrc = g_a32 + (size_t)img * 32768;
        float pool[4][2];
#pragma unroll
        for (int j = 0; j < 4; j++) { pool[j][0] = 0.f; pool[j][1] = 0.f; }

        c2_load_tile(sbase, gsrc, 0, 0, tid);
        asm volatile("cp.async.commit_group;" ::: "memory");

        for (int t = 0; t < 8; t++) {
            asm volatile("cp.async.wait_group 0;" ::: "memory");
            __syncthreads();          // data visible; all compute(t-1) done
            if (t < 7) {
                c2_load_tile(sbase, gsrc, t + 1, (t + 1) & 1, tid);  // overlaps compute
                asm volatile("cp.async.commit_group;" ::: "memory");
            }

            float acc[2][4][4];
#pragma unroll
            for (int f = 0; f < 2; f++)
#pragma unroll
                for (int j = 0; j < 4; j++)
#pragma unroll
                    for (int q = 0; q < 4; q++) acc[f][j][q] = 0.f;

            uint32_t aBase = sbase + ABUF_OFF + (uint32_t)((t & 1) * ABUF_SZ) +
                             (uint32_t)(m_idx * 4896) + aThr;
            uint32_t bBase = sbase + B_OFF + bThr;
#pragma unroll
            for (int s = 0; s < 9; s++) {
                const uint32_t doff = (uint32_t)((s / 3) * 4896 + (s % 3) * 144);
#pragma unroll
                for (int ks = 0; ks < 4; ks++) {
                    uint32_t a[2][4];
#pragma unroll
                    for (int f = 0; f < 2; f++)
                        ldmx4(a[f][0], a[f][1], a[f][2], a[f][3],
                              aBase + doff + (uint32_t)(f * 2304 + ks * 32));
                    uint32_t kofs = (uint32_t)(s * 128 + ks * 32);
#pragma unroll
                    for (int fp = 0; fp < 2; fp++) {
                        uint32_t r0, r1, r2, r3;
                        ldmx4(r0, r1, r2, r3, bBase + (uint32_t)(fp * 18688) + kofs);
#pragma unroll
                        for (int f = 0; f < 2; f++) {
                            mma16816(acc[f][fp * 2], a[f], r0, r1);
                            mma16816(acc[f][fp * 2 + 1], a[f], r2, r3);
                        }
                    }
                }
            }
            // bias + relu + pixel-pool
#pragma unroll
            for (int f = 0; f < 2; f++)
#pragma unroll
                for (int j = 0; j < 4; j++) {
                    pool[j][0] += fmaxf(acc[f][j][0] + bv[j][0], 0.f) +
                                  fmaxf(acc[f][j][2] + bv[j][0], 0.f);
                    pool[j][1] += fmaxf(acc[f][j][1] + bv[j][1], 0.f) +
                                  fmaxf(acc[f][j][3] + bv[j][1], 0.f);
                }
        }
        // reduce over lanes with same (lane&3)
#pragma unroll
        for (int off = 4; off <= 16; off <<= 1)
#pragma unroll
            for (int j = 0; j < 4; j++) {
                pool[j][0] += __shfl_xor_sync(0xffffffffu, pool[j][0], off);
                pool[j][1] += __shfl_xor_sync(0xffffffffu, pool[j][1], off);
            }
        if (lane < 4) {
            float* sp = sPool + wid * 32;
#pragma unroll
            for (int j = 0; j < 4; j++) {
                sp[j * 8 + lane * 2] = pool[j][0];
                sp[j * 8 + lane * 2 + 1] = pool[j][1];
            }
        }
        __syncthreads();
        if (tid < 128) {
            int ni = tid >> 5, col = tid & 31;
            float s = 0.f;
#pragma unroll
            for (int m = 0; m < 4; m++) s += sPool[(ni * 4 + m) * 32 + col];
            g_pool[img * 128 + tid] = s * (1.f / 1024.f);
        }
    }
}

// ---------------- fused tail: fc + mask + colsum + sage1 + colsum + sage2 ----------------
static constexpr int TP_POOL = 0;       // 32 x 128
static constexpr int TP_H    = 4096;    // 32 x 256 (reused as sage2 partials)
static constexpr int TP_O1   = 12288;   // 32 x 256
static constexpr int TP_CS   = 20480;   // 256
static constexpr int TP_B2   = 20736;   // 256
static constexpr int TP_MASK = 20992;   // 32
static constexpr int TAIL_SMEM = 21024 * 4;

__global__ __launch_bounds__(256) void tail_kernel(
    const float* __restrict__ fc_w, const float* __restrict__ fc_b,
    const float* __restrict__ mask,
    const float* __restrict__ s1_lw, const float* __restrict__ s1_lb,
    const float* __restrict__ s1_rw,
    const float* __restrict__ s2_lw, const float* __restrict__ s2_lb,
    const float* __restrict__ s2_rw,
    float* __restrict__ out) {
    extern __shared__ float sm[];
    float* sPool = sm + TP_POOL;
    float* sH    = sm + TP_H;
    float* sO1   = sm + TP_O1;
    float* sCs   = sm + TP_CS;
    float* sB2   = sm + TP_B2;
    float* sMask = sm + TP_MASK;
    int b = blockIdx.x, tid = threadIdx.x;

    for (int e = tid; e < 4096; e += 256) sPool[e] = g_pool[b * 4096 + e];
    if (tid < 32) sMask[tid] = mask[b * 32 + tid];
    __syncthreads();

    // fc: thread = output dim o (256); 32 nodes in registers
    {
        float acc[32];
#pragma unroll
        for (int n = 0; n < 32; n++) acc[n] = 0.f;
        const float4* wrow = reinterpret_cast<const float4*>(fc_w + tid * 128);
#pragma unroll 4
        for (int k4 = 0; k4 < 32; k4++) {
            float4 wv = wrow[k4];
#pragma unroll
            for (int n = 0; n < 32; n++) {
                float4 hv = *reinterpret_cast<const float4*>(sPool + n * 128 + k4 * 4);
                acc[n] += wv.x * hv.x + wv.y * hv.y + wv.z * hv.z + wv.w * hv.w;
            }
        }
        float fb = fc_b[tid];
#pragma unroll
        for (int n = 0; n < 32; n++) sH[n * 256 + tid] = (acc[n] + fb) * sMask[n];
    }
    __syncthreads();
    {
        float s = 0.f;
#pragma unroll
        for (int n = 0; n < 32; n++) s += sH[n * 256 + tid];
        sCs[tid] = s;
    }
    __syncthreads();

    // sage1
    {
        float acc[32];
#pragma unroll
        for (int n = 0; n < 32; n++) acc[n] = 0.f;
        float bacc = 0.f;
        const float4* lw4 = reinterpret_cast<const float4*>(s1_lw + tid * 256);
        const float4* rw4 = reinterpret_cast<const float4*>(s1_rw + tid * 256);
#pragma unroll 2
        for (int k4 = 0; k4 < 64; k4++) {
            float4 lw = lw4[k4], rw = rw4[k4];
            float4 cs = *reinterpret_cast<const float4*>(sCs + k4 * 4);
            bacc += cs.x * lw.x + cs.y * lw.y + cs.z * lw.z + cs.w * lw.w;
            float4 wc;
            wc.x = rw.x - lw.x * (1.f / 31.f); wc.y = rw.y - lw.y * (1.f / 31.f);
            wc.z = rw.z - lw.z * (1.f / 31.f); wc.w = rw.w - lw.w * (1.f / 31.f);
#pragma unroll
            for (int n = 0; n < 32; n++) {
                float4 hv = *reinterpret_cast<const float4*>(sH + n * 256 + k4 * 4);
                acc[n] += wc.x * hv.x + wc.y * hv.y + wc.z * hv.z + wc.w * hv.w;
            }
        }
        float base = s1_lb[tid] + bacc * (1.f / 31.f);
#pragma unroll
        for (int n = 0; n < 32; n++) sO1[n * 256 + tid] = fmaxf(base + acc[n], 0.f);
    }
    __syncthreads();
    {
        float s = 0.f;
#pragma unroll
        for (int n = 0; n < 32; n++) s += sO1[n * 256 + tid];
        sCs[tid] = s;
    }
    __syncthreads();

    // sage2: o2 = tid&127, k-half = tid>>7
    {
        int o2 = tid & 127, half = tid >> 7;
        float acc[32];
#pragma unroll
        for (int n = 0; n < 32; n++) acc[n] = 0.f;
        float bacc = 0.f;
        const float4* lw4 = reinterpret_cast<const float4*>(s2_lw + o2 * 256 + half * 128);
        const float4* rw4 = reinterpret_cast<const float4*>(s2_rw + o2 * 256 + half * 128);
        const float* csb = sCs + half * 128;
        const float* o1b = sO1 + half * 128;
#pragma unroll 2
        for (int k4 = 0; k4 < 32; k4++) {
            float4 lw = lw4[k4], rw = rw4[k4];
            float4 cs = *reinterpret_cast<const float4*>(csb + k4 * 4);
            bacc += cs.x * lw.x + cs.y * lw.y + cs.z * lw.z + cs.w * lw.w;
            float4 wc;
            wc.x = rw.x - lw.x * (1.f / 31.f); wc.y = rw.y - lw.y * (1.f / 31.f);
            wc.z = rw.z - lw.z * (1.f / 31.f); wc.w = rw.w - lw.w * (1.f / 31.f);
#pragma unroll
            for (int n = 0; n < 32; n++) {
                float4 hv = *reinterpret_cast<const float4*>(o1b + n * 256 + k4 * 4);
                acc[n] += wc.x * hv.x + wc.y * hv.y + wc.z * hv.z + wc.w * hv.w;
            }
        }
#pragma unroll
        for (int n = 0; n < 32; n++) sH[n * 256 + tid] = acc[n];
        sB2[tid] = bacc;
    }
    __syncthreads();
    for (int e = tid; e < 4096; e += 256) {
        int n = e >> 7, o2 = e & 127;
        float v = sH[n * 256 + o2] + sH[n * 256 + o2 + 128];
        float base = s2_lb[o2] + (sB2[o2] + sB2[o2 + 128]) * (1.f / 31.f);
        out[(b * 32 + n) * 128 + o2] = base + v;
    }
}

// ---------------- launch ----------------
extern "C" void kernel_launch(void* const* d_in, const int* in_sizes, int n_in,
                              void* d_out, int out_size) {
    const float* x       = (const float*)d_in[0];
    const float* mask    = (const float*)d_in[1];
    const float* conv1_w = (const float*)d_in[2];
    const float* conv1_b = (const float*)d_in[3];
    const float* conv2_w = (const float*)d_in[4];
    const float* conv2_b = (const float*)d_in[5];
    const float* fc_w    = (const float*)d_in[6];
    const float* fc_b    = (const float*)d_in[7];
    const float* s1_lw   = (const float*)d_in[8];
    const float* s1_lb   = (const float*)d_in[9];
    const float* s1_rw   = (const float*)d_in[10];
    const float* s2_lw   = (const float*)d_in[11];
    const float* s2_lb   = (const float*)d_in[12];
    const float* s2_rw   = (const float*)d_in[13];
    float* out = (float*)d_out;

    cudaFuncSetAttribute(conv1_kernel, cudaFuncAttributeMaxDynamicSharedMemorySize, C1_SMEM);
    cudaFuncSetAttribute(conv2_mma_kernel, cudaFuncAttributeMaxDynamicSharedMemorySize,
                         SMEM2_TOTAL);
    cudaFuncSetAttribute(tail_kernel, cudaFuncAttributeMaxDynamicSharedMemorySize, TAIL_SMEM);

    conv1_kernel<<<1024, 512, C1_SMEM>>>(x, conv1_w, conv1_b);
    conv2_mma_kernel<<<148, 512, SMEM2_TOTAL>>>(conv2_w, conv2_b);
    tail_kernel<<<32, 256, TAIL_SMEM>>>(fc_w, fc_b, mask, s1_lw, s1_lb, s1_rw,
                                        s2_lw, s2_lb, s2_rw, out);
}

// round 12
// speedup vs baseline: 1.3943x; 1.0292x over previous
#include <cuda_runtime.h>
#include <cuda_fp16.h>
#include <cstdint>

// ---------------- scratch (__device__ globals; no allocation) ----------------
// layout: [img][ocGroup 0..3][px 0..1023][8 words of 16 fp16 ch]
__device__ uint32_t g_a32[1024 * 32768];   // conv1 output (134MB)
__device__ float g_pool[1024 * 128];       // pooled conv2 features

// ---------------- helpers ----------------
__device__ __forceinline__ uint32_t smem_u32(const void* p) {
    uint32_t a;
    asm("{ .reg .u64 t; cvta.to.shared.u64 t, %1; cvt.u32.u64 %0, t; }" : "=r"(a) : "l"(p));
    return a;
}
__device__ __forceinline__ uint32_t pack_h2(float a, float b) {
    __half2 t = __floats2half2_rn(a, b);
    return *reinterpret_cast<uint32_t*>(&t);
}
__device__ __forceinline__ void ldmx4(uint32_t& r0, uint32_t& r1, uint32_t& r2, uint32_t& r3,
                                      uint32_t addr) {
    asm volatile("ldmatrix.sync.aligned.m8n8.x4.shared.b16 {%0,%1,%2,%3}, [%4];"
                 : "=r"(r0), "=r"(r1), "=r"(r2), "=r"(r3) : "r"(addr));
}
__device__ __forceinline__ void mma16816(float* c, const uint32_t* a, uint32_t b0, uint32_t b1) {
    asm volatile(
        "mma.sync.aligned.m16n8k16.row.col.f32.f16.f16.f32 "
        "{%0,%1,%2,%3}, {%4,%5,%6,%7}, {%8,%9}, {%0,%1,%2,%3};"
        : "+f"(c[0]), "+f"(c[1]), "+f"(c[2]), "+f"(c[3])
        : "r"(a[0]), "r"(a[1]), "r"(a[2]), "r"(a[3]), "r"(b0), "r"(b1));
}

// ---------------- conv1 (3->64, 3x3 SAME) + ReLU -> grouped NHWC fp16 ----------------
// plain FFMA (proven fastest), 4 px/thread, staged coalesced stores.
// dynamic smem: sIn 3072f | sW 1728f | sB 64f | stage 9216w = 56320 bytes
static constexpr int C1_SMEM = 56320;

__global__ __launch_bounds__(256) void conv1_kernel(const float* __restrict__ x,
                                                    const float* __restrict__ w,
                                                    const float* __restrict__ bias) {
    extern __shared__ float c1s[];
    float* sIn = c1s;                  // 3072
    float* sW  = c1s + 3072;           // 1728  [kt][oc]
    float* sB  = c1s + 4800;           // 64
    uint32_t* stage = reinterpret_cast<uint32_t*>(c1s + 4864);  // 1024 px * 9 words

    int img = blockIdx.x, tid = threadIdx.x;
    for (int j = tid; j < 3072; j += 256) sIn[j] = x[img * 3072 + j];
    for (int e = tid; e < 1728; e += 256) { int k = e >> 6, o = e & 63; sW[e] = w[o * 27 + k]; }
    if (tid < 64) sB[tid] = bias[tid];
    __syncthreads();
    int r = tid >> 3, x0 = (tid & 7) << 2;

    for (int oc0 = 0; oc0 < 64; oc0 += 16) {
        float acc[4][16];
#pragma unroll
        for (int p = 0; p < 4; p++)
#pragma unroll
            for (int o = 0; o < 16; o++) acc[p][o] = sB[oc0 + o];
#pragma unroll
        for (int ic = 0; ic < 3; ic++) {
#pragma unroll
            for (int ky = 0; ky < 3; ky++) {
                int yy = r + ky - 1;
                float iv[6];
                if ((unsigned)yy < 32u) {
                    const float* row = sIn + ic * 1024 + yy * 32;
#pragma unroll
                    for (int j = 0; j < 6; j++) {
                        int xx = x0 - 1 + j;
                        iv[j] = ((unsigned)xx < 32u) ? row[xx] : 0.f;
                    }
                } else {
#pragma unroll
                    for (int j = 0; j < 6; j++) iv[j] = 0.f;
                }
#pragma unroll
                for (int kx = 0; kx < 3; kx++) {
                    const float* wp = sW + (ic * 9 + ky * 3 + kx) * 64 + oc0;
                    float wv[16];
#pragma unroll
                    for (int o = 0; o < 16; o++) wv[o] = wp[o];
#pragma unroll
                    for (int p = 0; p < 4; p++) {
                        float v = iv[p + kx];
#pragma unroll
                        for (int o = 0; o < 16; o++) acc[p][o] = fmaf(v, wv[o], acc[p][o]);
                    }
                }
            }
        }
        // stage (XOR-swizzled, conflict-free) then flush coalesced
        __syncthreads();   // previous group's flush readers done
#pragma unroll
        for (int p = 0; p < 4; p++) {
            int pix = r * 32 + x0 + p;
            int xr = (pix >> 5) & 7;
            uint32_t* st = stage + pix * 9;
#pragma unroll
            for (int oo = 0; oo < 8; oo++)
                st[oo ^ xr] = pack_h2(fmaxf(acc[p][2 * oo], 0.f),
                                      fmaxf(acc[p][2 * oo + 1], 0.f));
        }
        __syncthreads();
        {
            int g = oc0 >> 4;
            uint4* dst = reinterpret_cast<uint4*>(g_a32 + (size_t)img * 32768 + g * 8192);
            int px0 = tid >> 1, w0 = (tid & 1) * 4;
#pragma unroll
            for (int k4 = 0; k4 < 8; k4++) {
                int px = px0 + k4 * 128;
                int xr = (px >> 5) & 7;
                const uint32_t* st = stage + px * 9;
                uint4 v;
                v.x = st[(w0 + 0) ^ xr];
                v.y = st[(w0 + 1) ^ xr];
                v.z = st[(w0 + 2) ^ xr];
                v.w = st[(w0 + 3) ^ xr];
                dst[tid + k4 * 256] = v;
            }
        }
    }
}

// ---------------- conv2 via mma.sync fp16: 8 warps 4m x 2n (192B/MMA), ping-pong ------
// SMEM: B 149504 | 2 x A buf (6 rows x 34 px x 144B = 29376) | bias 512 | pool 2048
static constexpr int B_OFF = 0;
static constexpr int ABUF_OFF = 149504;
static constexpr int ABUF_SZ = 29376;
static constexpr int SBIAS_OFF = 208256;
static constexpr int SPOOL_OFF = 208768;
static constexpr int SMEM2_TOTAL = 210816;

// load 6 rows (4 + 2 halo) of tile t into buffer b (256 threads)
__device__ __forceinline__ void c2_load_tile(uint32_t sbase, const uint32_t* gsrc,
                                             int t, int b, int tid) {
#pragma unroll
    for (int i = 0; i < 6; i++) {
        int c = tid + i * 256;
        int wr = c >> 8, rem = c & 255;
        int px = rem >> 3, g = (rem >> 1) & 3, q = rem & 1;
        int gy = t * 4 + wr - 1;
        uint32_t ok = ((unsigned)gy < 32u) ? 16u : 0u;
        int gyc = gy < 0 ? 0 : (gy > 31 ? 31 : gy);
        const void* gp = gsrc + g * 8192 + (gyc * 32 + px) * 8 + q * 4;
        uint32_t sd = sbase + ABUF_OFF + (uint32_t)(b * ABUF_SZ) +
                      (uint32_t)(wr * 4896 + (px + 1) * 144 + g * 32 + q * 16);
        asm volatile("cp.async.cg.shared.global [%0], [%1], 16, %2;"
                     :: "r"(sd), "l"(gp), "r"(ok) : "memory");
    }
}

__global__ __launch_bounds__(256, 1) void conv2_mma_kernel(const float* __restrict__ w,
                                                           const float* __restrict__ bias) {
    extern __shared__ __align__(16) char smem[];
    uint32_t sbase = smem_u32(smem);
    float* sBias = reinterpret_cast<float*>(smem + SBIAS_OFF);
    float* sPool = reinterpret_cast<float*>(smem + SPOOL_OFF);
    int tid = threadIdx.x, lane = tid & 31, wid = tid >> 5;
    int m_idx = wid & 3, n_idx = wid >> 2;   // 4 m-warps (32px row) x 2 n-warps (64oc)

    // zero x-halo pixels (px cols 0, 33) of both buffers, 6 rows each
    for (int e = tid; e < 864; e += 256) {
        int b = e / 432, rem = e % 432;
        int rr = rem / 72, rem2 = rem % 72;
        int side = rem2 / 36, q = rem2 % 36;
        *reinterpret_cast<uint32_t*>(smem + ABUF_OFF + b * ABUF_SZ + rr * 4896 +
                                     (side ? 33 : 0) * 144 + q * 4) = 0u;
    }
    // build B: sB[n][k], k = s*64 + ic, k-stride padded to 584 elems (fp16)
    for (int e = tid; e < 73728; e += 256) {
        int n = e / 576, k = e - n * 576;
        int ic = k & 63, s = k >> 6;
        float v = w[n * 576 + ic * 9 + s];
        *reinterpret_cast<__half*>(smem + B_OFF + (n * 584 + k) * 2) = __float2half(v);
    }
    if (tid < 128) sBias[tid] = bias[tid];
    __syncthreads();

    // per-thread ldmatrix address components
    uint32_t aThr = (uint32_t)((lane & 15) * 144 + ((lane >> 4) & 1) * 16);
    uint32_t bThr = (uint32_t)(((((lane >> 4) & 1) * 8 + (lane & 7)) * 584 +
                                ((lane >> 3) & 1) * 8) * 2 + n_idx * 74752);
    float bv[8][2];
#pragma unroll
    for (int j = 0; j < 8; j++) {
        bv[j][0] = sBias[n_idx * 64 + j * 8 + (lane & 3) * 2];
        bv[j][1] = sBias[n_idx * 64 + j * 8 + (lane & 3) * 2 + 1];
    }

    for (int img = blockIdx.x; img < 1024; img += gridDim.x) {
        const uint32_t* gsrc = g_a32 + (size_t)img * 32768;
        float pool[8][2];
#pragma unroll
        for (int j = 0; j < 8; j++) { pool[j][0] = 0.f; pool[j][1] = 0.f; }

        c2_load_tile(sbase, gsrc, 0, 0, tid);
        asm volatile("cp.async.commit_group;" ::: "memory");

        for (int t = 0; t < 8; t++) {
            asm volatile("cp.async.wait_group 0;" ::: "memory");
            __syncthreads();          // data visible; all compute(t-1) done
            if (t < 7) {
                c2_load_tile(sbase, gsrc, t + 1, (t + 1) & 1, tid);  // overlaps compute
                asm volatile("cp.async.commit_group;" ::: "memory");
            }

            float acc[2][8][4];
#pragma unroll
            for (int f = 0; f < 2; f++)
#pragma unroll
                for (int j = 0; j < 8; j++)
#pragma unroll
                    for (int q = 0; q < 4; q++) acc[f][j][q] = 0.f;

            uint32_t aBase = sbase + ABUF_OFF + (uint32_t)((t & 1) * ABUF_SZ) +
                             (uint32_t)(m_idx * 4896) + aThr;
            uint32_t bBase = sbase + B_OFF + bThr;
#pragma unroll
            for (int s = 0; s < 9; s++) {
                const uint32_t doff = (uint32_t)((s / 3) * 4896 + (s % 3) * 144);
#pragma unroll
                for (int ks = 0; ks < 4; ks++) {
                    uint32_t a[2][4];
#pragma unroll
                    for (int f = 0; f < 2; f++)
                        ldmx4(a[f][0], a[f][1], a[f][2], a[f][3],
                              aBase + doff + (uint32_t)(f * 2304 + ks * 32));
                    uint32_t kofs = (uint32_t)(s * 128 + ks * 32);
#pragma unroll
                    for (int fp = 0; fp < 4; fp++) {
                        uint32_t r0, r1, r2, r3;
                        ldmx4(r0, r1, r2, r3, bBase + (uint32_t)(fp * 18688) + kofs);
#pragma unroll
                        for (int f = 0; f < 2; f++) {
                            mma16816(acc[f][fp * 2], a[f], r0, r1);
                            mma16816(acc[f][fp * 2 + 1], a[f], r2, r3);
                        }
                    }
                }
            }
            // bias + relu + pixel-pool
#pragma unroll
            for (int f = 0; f < 2; f++)
#pragma unroll
                for (int j = 0; j < 8; j++) {
                    pool[j][0] += fmaxf(acc[f][j][0] + bv[j][0], 0.f) +
                                  fmaxf(acc[f][j][2] + bv[j][0], 0.f);
                    pool[j][1] += fmaxf(acc[f][j][1] + bv[j][1], 0.f) +
                                  fmaxf(acc[f][j][3] + bv[j][1], 0.f);
                }
        }
        // reduce over lanes with same (lane&3)
#pragma unroll
        for (int off = 4; off <= 16; off <<= 1)
#pragma unroll
            for (int j = 0; j < 8; j++) {
                pool[j][0] += __shfl_xor_sync(0xffffffffu, pool[j][0], off);
                pool[j][1] += __shfl_xor_sync(0xffffffffu, pool[j][1], off);
            }
        if (lane < 4) {
            float* sp = sPool + wid * 64;
#pragma unroll
            for (int j = 0; j < 8; j++) {
                sp[j * 8 + lane * 2] = pool[j][0];
                sp[j * 8 + lane * 2 + 1] = pool[j][1];
            }
        }
        __syncthreads();
        if (tid < 128) {
            int ni = tid >> 6, col = tid & 63;
            float s = 0.f;
#pragma unroll
            for (int m = 0; m < 4; m++) s += sPool[(ni * 4 + m) * 64 + col];
            g_pool[img * 128 + ni * 64 + col] = s * (1.f / 1024.f);
        }
    }
}

// ---------------- fused tail: fc + mask + colsum + sage1 + colsum + sage2 ----------------
static constexpr int TP_POOL = 0;       // 32 x 128
static constexpr int TP_H    = 4096;    // 32 x 256 (reused as sage2 partials)
static constexpr int TP_O1   = 12288;   // 32 x 256
static constexpr int TP_CS   = 20480;   // 256
static constexpr int TP_B2   = 20736;   // 256
static constexpr int TP_MASK = 20992;   // 32
static constexpr int TAIL_SMEM = 21024 * 4;

__global__ __launch_bounds__(256) void tail_kernel(
    const float* __restrict__ fc_w, const float* __restrict__ fc_b,
    const float* __restrict__ mask,
    const float* __restrict__ s1_lw, const float* __restrict__ s1_lb,
    const float* __restrict__ s1_rw,
    const float* __restrict__ s2_lw, const float* __restrict__ s2_lb,
    const float* __restrict__ s2_rw,
    float* __restrict__ out) {
    extern __shared__ float sm[];
    float* sPool = sm + TP_POOL;
    float* sH    = sm + TP_H;
    float* sO1   = sm + TP_O1;
    float* sCs   = sm + TP_CS;
    float* sB2   = sm + TP_B2;
    float* sMask = sm + TP_MASK;
    int b = blockIdx.x, tid = threadIdx.x;

    for (int e = tid; e < 4096; e += 256) sPool[e] = g_pool[b * 4096 + e];
    if (tid < 32) sMask[tid] = mask[b * 32 + tid];
    __syncthreads();

    // fc: thread = output dim o (256); 32 nodes in registers
    {
        float acc[32];
#pragma unroll
        for (int n = 0; n < 32; n++) acc[n] = 0.f;
        const float4* wrow = reinterpret_cast<const float4*>(fc_w + tid * 128);
#pragma unroll 4
        for (int k4 = 0; k4 < 32; k4++) {
            float4 wv = wrow[k4];
#pragma unroll
            for (int n = 0; n < 32; n++) {
                float4 hv = *reinterpret_cast<const float4*>(sPool + n * 128 + k4 * 4);
                acc[n] += wv.x * hv.x + wv.y * hv.y + wv.z * hv.z + wv.w * hv.w;
            }
        }
        float fb = fc_b[tid];
#pragma unroll
        for (int n = 0; n < 32; n++) sH[n * 256 + tid] = (acc[n] + fb) * sMask[n];
    }
    __syncthreads();
    {
        float s = 0.f;
#pragma unroll
        for (int n = 0; n < 32; n++) s += sH[n * 256 + tid];
        sCs[tid] = s;
    }
    __syncthreads();

    // sage1
    {
        float acc[32];
#pragma unroll
        for (int n = 0; n < 32; n++) acc[n] = 0.f;
        float bacc = 0.f;
        const float4* lw4 = reinterpret_cast<const float4*>(s1_lw + tid * 256);
        const float4* rw4 = reinterpret_cast<const float4*>(s1_rw + tid * 256);
#pragma unroll 2
        for (int k4 = 0; k4 < 64; k4++) {
            float4 lw = lw4[k4], rw = rw4[k4];
            float4 cs = *reinterpret_cast<const float4*>(sCs + k4 * 4);
            bacc += cs.x * lw.x + cs.y * lw.y + cs.z * lw.z + cs.w * lw.w;
            float4 wc;
            wc.x = rw.x - lw.x * (1.f / 31.f); wc.y = rw.y - lw.y * (1.f / 31.f);
            wc.z = rw.z - lw.z * (1.f / 31.f); wc.w = rw.w - lw.w * (1.f / 31.f);
#pragma unroll
            for (int n = 0; n < 32; n++) {
                float4 hv = *reinterpret_cast<const float4*>(sH + n * 256 + k4 * 4);
                acc[n] += wc.x * hv.x + wc.y * hv.y + wc.z * hv.z + wc.w * hv.w;
            }
        }
        float base = s1_lb[tid] + bacc * (1.f / 31.f);
#pragma unroll
        for (int n = 0; n < 32; n++) sO1[n * 256 + tid] = fmaxf(base + acc[n], 0.f);
    }
    __syncthreads();
    {
        float s = 0.f;
#pragma unroll
        for (int n = 0; n < 32; n++) s += sO1[n * 256 + tid];
        sCs[tid] = s;
    }
    __syncthreads();

    // sage2: o2 = tid&127, k-half = tid>>7
    {
        int o2 = tid & 127, half = tid >> 7;
        float acc[32];
#pragma unroll
        for (int n = 0; n < 32; n++) acc[n] = 0.f;
        float bacc = 0.f;
        const float4* lw4 = reinterpret_cast<const float4*>(s2_lw + o2 * 256 + half * 128);
        const float4* rw4 = reinterpret_cast<const float4*>(s2_rw + o2 * 256 + half * 128);
        const float* csb = sCs + half * 128;
        const float* o1b = sO1 + half * 128;
#pragma unroll 2
        for (int k4 = 0; k4 < 32; k4++) {
            float4 lw = lw4[k4], rw = rw4[k4];
            float4 cs = *reinterpret_cast<const float4*>(csb + k4 * 4);
            bacc += cs.x * lw.x + cs.y * lw.y + cs.z * lw.z + cs.w * lw.w;
            float4 wc;
            wc.x = rw.x - lw.x * (1.f / 31.f); wc.y = rw.y - lw.y * (1.f / 31.f);
            wc.z = rw.z - lw.z * (1.f / 31.f); wc.w = rw.w - lw.w * (1.f / 31.f);
#pragma unroll
            for (int n = 0; n < 32; n++) {
                float4 hv = *reinterpret_cast<const float4*>(o1b + n * 256 + k4 * 4);
                acc[n] += wc.x * hv.x + wc.y * hv.y + wc.z * hv.z + wc.w * hv.w;
            }
        }
#pragma unroll
        for (int n = 0; n < 32; n++) sH[n * 256 + tid] = acc[n];
        sB2[tid] = bacc;
    }
    __syncthreads();
    for (int e = tid; e < 4096; e += 256) {
        int n = e >> 7, o2 = e & 127;
        float v = sH[n * 256 + o2] + sH[n * 256 + o2 + 128];
        float base = s2_lb[o2] + (sB2[o2] + sB2[o2 + 128]) * (1.f / 31.f);
        out[(b * 32 + n) * 128 + o2] = base + v;
    }
}

// ---------------- launch ----------------
extern "C" void kernel_launch(void* const* d_in, const int* in_sizes, int n_in,
                              void* d_out, int out_size) {
    const float* x       = (const float*)d_in[0];
    const float* mask    = (const float*)d_in[1];
    const float* conv1_w = (const float*)d_in[2];
    const float* conv1_b = (const float*)d_in[3];
    const float* conv2_w = (const float*)d_in[4];
    const float* conv2_b = (const float*)d_in[5];
    const float* fc_w    = (const float*)d_in[6];
    const float* fc_b    = (const float*)d_in[7];
    const float* s1_lw   = (const float*)d_in[8];
    const float* s1_lb   = (const float*)d_in[9];
    const float* s1_rw   = (const float*)d_in[10];
    const float* s2_lw   = (const float*)d_in[11];
    const float* s2_lb   = (const float*)d_in[12];
    const float* s2_rw   = (const float*)d_in[13];
    float* out = (float*)d_out;

    cudaFuncSetAttribute(conv1_kernel, cudaFuncAttributeMaxDynamicSharedMemorySize, C1_SMEM);
    cudaFuncSetAttribute(conv2_mma_kernel, cudaFuncAttributeMaxDynamicSharedMemorySize,
                         SMEM2_TOTAL);
    cudaFuncSetAttribute(tail_kernel, cudaFuncAttributeMaxDynamicSharedMemorySize, TAIL_SMEM);

    conv1_kernel<<<1024, 256, C1_SMEM>>>(x, conv1_w, conv1_b);
    conv2_mma_kernel<<<148, 256, SMEM2_TOTAL>>>(conv2_w, conv2_b);
    tail_kernel<<<32, 256, TAIL_SMEM>>>(fc_w, fc_b, mask, s1_lw, s1_lb, s1_rw,
                                        s2_lw, s2_lb, s2_rw, out);
}

// round 13
// speedup vs baseline: 1.4468x; 1.0377x over previous
#include <cuda_runtime.h>
#include <cuda_fp16.h>
#include <cstdint>

// ---------------- scratch (__device__ globals; no allocation) ----------------
// layout: [img][ocGroup 0..3][px 0..1023][8 words of 16 fp16 ch]
__device__ uint32_t g_a32[1024 * 32768];   // conv1 output (134MB)
__device__ float g_pool[1024 * 128];       // pooled conv2 features

// ---------------- helpers ----------------
__device__ __forceinline__ uint32_t smem_u32(const void* p) {
    uint32_t a;
    asm("{ .reg .u64 t; cvta.to.shared.u64 t, %1; cvt.u32.u64 %0, t; }" : "=r"(a) : "l"(p));
    return a;
}
__device__ __forceinline__ uint32_t pack_h2(float a, float b) {
    __half2 t = __floats2half2_rn(a, b);
    return *reinterpret_cast<uint32_t*>(&t);
}
__device__ __forceinline__ void ldmx4(uint32_t& r0, uint32_t& r1, uint32_t& r2, uint32_t& r3,
                                      uint32_t addr) {
    asm volatile("ldmatrix.sync.aligned.m8n8.x4.shared.b16 {%0,%1,%2,%3}, [%4];"
                 : "=r"(r0), "=r"(r1), "=r"(r2), "=r"(r3) : "r"(addr));
}
__device__ __forceinline__ void mma16816(float* c, const uint32_t* a, uint32_t b0, uint32_t b1) {
    asm volatile(
        "mma.sync.aligned.m16n8k16.row.col.f32.f16.f16.f32 "
        "{%0,%1,%2,%3}, {%4,%5,%6,%7}, {%8,%9}, {%0,%1,%2,%3};"
        : "+f"(c[0]), "+f"(c[1]), "+f"(c[2]), "+f"(c[3])
        : "r"(a[0]), "r"(a[1]), "r"(a[2]), "r"(a[3]), "r"(b0), "r"(b1));
}
__device__ __forceinline__ void half_bar(int barid) {
    asm volatile("bar.sync %0, %1;" :: "r"(barid), "r"(256) : "memory");
}

// ---------------- conv1 (3->64, 3x3 SAME) + ReLU -> grouped NHWC fp16 ----------------
// plain FFMA (proven fastest), 4 px/thread, staged coalesced stores.
static constexpr int C1_SMEM = 56320;

__global__ __launch_bounds__(256) void conv1_kernel(const float* __restrict__ x,
                                                    const float* __restrict__ w,
                                                    const float* __restrict__ bias) {
    extern __shared__ float c1s[];
    float* sIn = c1s;                  // 3072
    float* sW  = c1s + 3072;           // 1728  [kt][oc]
    float* sB  = c1s + 4800;           // 64
    uint32_t* stage = reinterpret_cast<uint32_t*>(c1s + 4864);  // 1024 px * 9 words

    int img = blockIdx.x, tid = threadIdx.x;
    for (int j = tid; j < 3072; j += 256) sIn[j] = x[img * 3072 + j];
    for (int e = tid; e < 1728; e += 256) { int k = e >> 6, o = e & 63; sW[e] = w[o * 27 + k]; }
    if (tid < 64) sB[tid] = bias[tid];
    __syncthreads();
    int r = tid >> 3, x0 = (tid & 7) << 2;

    for (int oc0 = 0; oc0 < 64; oc0 += 16) {
        float acc[4][16];
#pragma unroll
        for (int p = 0; p < 4; p++)
#pragma unroll
            for (int o = 0; o < 16; o++) acc[p][o] = sB[oc0 + o];
#pragma unroll
        for (int ic = 0; ic < 3; ic++) {
#pragma unroll
            for (int ky = 0; ky < 3; ky++) {
                int yy = r + ky - 1;
                float iv[6];
                if ((unsigned)yy < 32u) {
                    const float* row = sIn + ic * 1024 + yy * 32;
#pragma unroll
                    for (int j = 0; j < 6; j++) {
                        int xx = x0 - 1 + j;
                        iv[j] = ((unsigned)xx < 32u) ? row[xx] : 0.f;
                    }
                } else {
#pragma unroll
                    for (int j = 0; j < 6; j++) iv[j] = 0.f;
                }
#pragma unroll
                for (int kx = 0; kx < 3; kx++) {
                    const float* wp = sW + (ic * 9 + ky * 3 + kx) * 64 + oc0;
                    float wv[16];
#pragma unroll
                    for (int o = 0; o < 16; o++) wv[o] = wp[o];
#pragma unroll
                    for (int p = 0; p < 4; p++) {
                        float v = iv[p + kx];
#pragma unroll
                        for (int o = 0; o < 16; o++) acc[p][o] = fmaf(v, wv[o], acc[p][o]);
                    }
                }
            }
        }
        __syncthreads();   // previous group's flush readers done
#pragma unroll
        for (int p = 0; p < 4; p++) {
            int pix = r * 32 + x0 + p;
            int xr = (pix >> 5) & 7;
            uint32_t* st = stage + pix * 9;
#pragma unroll
            for (int oo = 0; oo < 8; oo++)
                st[oo ^ xr] = pack_h2(fmaxf(acc[p][2 * oo], 0.f),
                                      fmaxf(acc[p][2 * oo + 1], 0.f));
        }
        __syncthreads();
        {
            int g = oc0 >> 4;
            uint4* dst = reinterpret_cast<uint4*>(g_a32 + (size_t)img * 32768 + g * 8192);
            int px0 = tid >> 1, w0 = (tid & 1) * 4;
#pragma unroll
            for (int k4 = 0; k4 < 8; k4++) {
                int px = px0 + k4 * 128;
                int xr = (px >> 5) & 7;
                const uint32_t* st = stage + px * 9;
                uint4 v;
                v.x = st[(w0 + 0) ^ xr];
                v.y = st[(w0 + 1) ^ xr];
                v.z = st[(w0 + 2) ^ xr];
                v.w = st[(w0 + 3) ^ xr];
                dst[tid + k4 * 256] = v;
            }
        }
    }
}

// ---------------- conv2: two images in flight (2 halves x 8 warps), named barriers ----
// SMEM: B 149504 | 2 half-bufs (6 rows x 34 px x 144B = 29376) | bias 512 | pool 4096
static constexpr int B_OFF = 0;
static constexpr int ABUF_OFF = 149504;
static constexpr int ABUF_SZ = 29376;
static constexpr int SBIAS_OFF = 208256;
static constexpr int SPOOL_OFF = 208768;   // 16 warps x 64 floats
static constexpr int SMEM2_TOTAL = 212864;

__global__ __launch_bounds__(512, 1) void conv2_mma_kernel(const float* __restrict__ w,
                                                           const float* __restrict__ bias) {
    extern __shared__ __align__(16) char smem[];
    uint32_t sbase = smem_u32(smem);
    float* sBias = reinterpret_cast<float*>(smem + SBIAS_OFF);
    float* sPool = reinterpret_cast<float*>(smem + SPOOL_OFF);
    int tid = threadIdx.x, lane = tid & 31, wid = tid >> 5;
    int h = tid >> 8, ltid = tid & 255;
    int lwid = wid & 7;
    int m_idx = lwid & 3, n_idx = lwid >> 2;  // per half: 4 m-warps (32px) x 2 n-warps (64oc)
    int barid = h + 1;

    // zero x-halo pixels (px cols 0, 33) of both half-buffers, 6 rows each
    for (int e = tid; e < 864; e += 512) {
        int b = e / 432, rem = e % 432;
        int rr = rem / 72, rem2 = rem % 72;
        int side = rem2 / 36, q = rem2 % 36;
        *reinterpret_cast<uint32_t*>(smem + ABUF_OFF + b * ABUF_SZ + rr * 4896 +
                                     (side ? 33 : 0) * 144 + q * 4) = 0u;
    }
    // build B: sB[n][k], k = s*64 + ic, k-stride padded to 584 elems (fp16)
    for (int e = tid; e < 73728; e += 512) {
        int n = e / 576, k = e - n * 576;
        int ic = k & 63, s = k >> 6;
        float v = w[n * 576 + ic * 9 + s];
        *reinterpret_cast<__half*>(smem + B_OFF + (n * 584 + k) * 2) = __float2half(v);
    }
    if (tid < 128) sBias[tid] = bias[tid];
    __syncthreads();

    // per-thread ldmatrix address components
    uint32_t aThr = (uint32_t)((lane & 15) * 144 + ((lane >> 4) & 1) * 16);
    uint32_t bThr = (uint32_t)(((((lane >> 4) & 1) * 8 + (lane & 7)) * 584 +
                                ((lane >> 3) & 1) * 8) * 2 + n_idx * 74752);
    uint32_t abuf = sbase + ABUF_OFF + (uint32_t)(h * ABUF_SZ);

    // image split: block images img = blockIdx.x + 148*k, k in [0,K); half0 gets first ceil(K/2)
    int K = (1024 - blockIdx.x + 147) / 148;
    int kmid = (K + 1) >> 1;
    int kbeg = h ? kmid : 0;
    int kend = h ? K : kmid;

    for (int kk = kbeg; kk < kend; kk++) {
        int img = blockIdx.x + 148 * kk;
        const uint32_t* gsrc = g_a32 + (size_t)img * 32768;
        float pool[8][2];
#pragma unroll
        for (int j = 0; j < 8; j++) { pool[j][0] = 0.f; pool[j][1] = 0.f; }

        for (int t = 0; t < 8; t++) {
            half_bar(barid);   // this half's previous-tile reads done
            // load 6 rows (4 + 2 halo) into this half's buffer
#pragma unroll
            for (int i = 0; i < 6; i++) {
                int c = ltid + i * 256;
                int wr = c >> 8, rem = c & 255;
                int px = rem >> 3, g = (rem >> 1) & 3, q = rem & 1;
                int gy = t * 4 + wr - 1;
                uint32_t ok = ((unsigned)gy < 32u) ? 16u : 0u;
                int gyc = gy < 0 ? 0 : (gy > 31 ? 31 : gy);
                const void* gp = gsrc + g * 8192 + (gyc * 32 + px) * 8 + q * 4;
                uint32_t sd = abuf + (uint32_t)(wr * 4896 + (px + 1) * 144 + g * 32 + q * 16);
                asm volatile("cp.async.cg.shared.global [%0], [%1], 16, %2;"
                             :: "r"(sd), "l"(gp), "r"(ok) : "memory");
            }
            asm volatile("cp.async.commit_group;" ::: "memory");
            asm volatile("cp.async.wait_group 0;" ::: "memory");
            half_bar(barid);   // loads visible to whole half

            float acc[2][8][4];
#pragma unroll
            for (int f = 0; f < 2; f++)
#pragma unroll
                for (int j = 0; j < 8; j++)
#pragma unroll
                    for (int q = 0; q < 4; q++) acc[f][j][q] = 0.f;

            uint32_t aBase = abuf + (uint32_t)(m_idx * 4896) + aThr;
            uint32_t bBase = sbase + B_OFF + bThr;
#pragma unroll
            for (int s = 0; s < 9; s++) {
                const uint32_t doff = (uint32_t)((s / 3) * 4896 + (s % 3) * 144);
#pragma unroll
                for (int ks = 0; ks < 4; ks++) {
                    uint32_t a[2][4];
#pragma unroll
                    for (int f = 0; f < 2; f++)
                        ldmx4(a[f][0], a[f][1], a[f][2], a[f][3],
                              aBase + doff + (uint32_t)(f * 2304 + ks * 32));
                    uint32_t kofs = (uint32_t)(s * 128 + ks * 32);
#pragma unroll
                    for (int fp = 0; fp < 4; fp++) {
                        uint32_t r0, r1, r2, r3;
                        ldmx4(r0, r1, r2, r3, bBase + (uint32_t)(fp * 18688) + kofs);
#pragma unroll
                        for (int f = 0; f < 2; f++) {
                            mma16816(acc[f][fp * 2], a[f], r0, r1);
                            mma16816(acc[f][fp * 2 + 1], a[f], r2, r3);
                        }
                    }
                }
            }
            // bias (broadcast LDS) + relu + pixel-pool
#pragma unroll
            for (int j = 0; j < 8; j++) {
                float b0 = sBias[n_idx * 64 + j * 8 + (lane & 3) * 2];
                float b1 = sBias[n_idx * 64 + j * 8 + (lane & 3) * 2 + 1];
                pool[j][0] += fmaxf(acc[0][j][0] + b0, 0.f) + fmaxf(acc[0][j][2] + b0, 0.f) +
                              fmaxf(acc[1][j][0] + b0, 0.f) + fmaxf(acc[1][j][2] + b0, 0.f);
                pool[j][1] += fmaxf(acc[0][j][1] + b1, 0.f) + fmaxf(acc[0][j][3] + b1, 0.f) +
                              fmaxf(acc[1][j][1] + b1, 0.f) + fmaxf(acc[1][j][3] + b1, 0.f);
            }
        }
        // reduce over lanes with same (lane&3)
#pragma unroll
        for (int off = 4; off <= 16; off <<= 1)
#pragma unroll
            for (int j = 0; j < 8; j++) {
                pool[j][0] += __shfl_xor_sync(0xffffffffu, pool[j][0], off);
                pool[j][1] += __shfl_xor_sync(0xffffffffu, pool[j][1], off);
            }
        if (lane < 4) {
            float* sp = sPool + wid * 64;
#pragma unroll
            for (int j = 0; j < 8; j++) {
                sp[j * 8 + lane * 2] = pool[j][0];
                sp[j * 8 + lane * 2 + 1] = pool[j][1];
            }
        }
        half_bar(barid);
        if (ltid < 128) {
            int ni = ltid >> 6, col = ltid & 63;
            float s = 0.f;
#pragma unroll
            for (int m = 0; m < 4; m++) s += sPool[(h * 8 + ni * 4 + m) * 64 + col];
            g_pool[img * 128 + ni * 64 + col] = s * (1.f / 1024.f);
        }
    }
}

// ---------------- fused tail: fc + mask + colsum + sage1 + colsum + sage2 ----------------
static constexpr int TP_POOL = 0;       // 32 x 128
static constexpr int TP_H    = 4096;    // 32 x 256 (reused as sage2 partials)
static constexpr int TP_O1   = 12288;   // 32 x 256
static constexpr int TP_CS   = 20480;   // 256
static constexpr int TP_B2   = 20736;   // 256
static constexpr int TP_MASK = 20992;   // 32
static constexpr int TAIL_SMEM = 21024 * 4;

__global__ __launch_bounds__(256) void tail_kernel(
    const float* __restrict__ fc_w, const float* __restrict__ fc_b,
    const float* __restrict__ mask,
    const float* __restrict__ s1_lw, const float* __restrict__ s1_lb,
    const float* __restrict__ s1_rw,
    const float* __restrict__ s2_lw, const float* __restrict__ s2_lb,
    const float* __restrict__ s2_rw,
    float* __restrict__ out) {
    extern __shared__ float sm[];
    float* sPool = sm + TP_POOL;
    float* sH    = sm + TP_H;
    float* sO1   = sm + TP_O1;
    float* sCs   = sm + TP_CS;
    float* sB2   = sm + TP_B2;
    float* sMask = sm + TP_MASK;
    int b = blockIdx.x, tid = threadIdx.x;

    for (int e = tid; e < 4096; e += 256) sPool[e] = g_pool[b * 4096 + e];
    if (tid < 32) sMask[tid] = mask[b * 32 + tid];
    __syncthreads();

    // fc: thread = output dim o (256); 32 nodes in registers
    {
        float acc[32];
#pragma unroll
        for (int n = 0; n < 32; n++) acc[n] = 0.f;
        const float4* wrow = reinterpret_cast<const float4*>(fc_w + tid * 128);
#pragma unroll 4
        for (int k4 = 0; k4 < 32; k4++) {
            float4 wv = wrow[k4];
#pragma unroll
            for (int n = 0; n < 32; n++) {
                float4 hv = *reinterpret_cast<const float4*>(sPool + n * 128 + k4 * 4);
                acc[n] += wv.x * hv.x + wv.y * hv.y + wv.z * hv.z + wv.w * hv.w;
            }
        }
        float fb = fc_b[tid];
#pragma unroll
        for (int n = 0; n < 32; n++) sH[n * 256 + tid] = (acc[n] + fb) * sMask[n];
    }
    __syncthreads();
    {
        float s = 0.f;
#pragma unroll
        for (int n = 0; n < 32; n++) s += sH[n * 256 + tid];
        sCs[tid] = s;
    }
    __syncthreads();

    // sage1
    {
        float acc[32];
#pragma unroll
        for (int n = 0; n < 32; n++) acc[n] = 0.f;
        float bacc = 0.f;
        const float4* lw4 = reinterpret_cast<const float4*>(s1_lw + tid * 256);
        const float4* rw4 = reinterpret_cast<const float4*>(s1_rw + tid * 256);
#pragma unroll 2
        for (int k4 = 0; k4 < 64; k4++) {
            float4 lw = lw4[k4], rw = rw4[k4];
            float4 cs = *reinterpret_cast<const float4*>(sCs + k4 * 4);
            bacc += cs.x * lw.x + cs.y * lw.y + cs.z * lw.z + cs.w * lw.w;
            float4 wc;
            wc.x = rw.x - lw.x * (1.f / 31.f); wc.y = rw.y - lw.y * (1.f / 31.f);
            wc.z = rw.z - lw.z * (1.f / 31.f); wc.w = rw.w - lw.w * (1.f / 31.f);
#pragma unroll
            for (int n = 0; n < 32; n++) {
                float4 hv = *reinterpret_cast<const float4*>(sH + n * 256 + k4 * 4);
                acc[n] += wc.x * hv.x + wc.y * hv.y + wc.z * hv.z + wc.w * hv.w;
            }
        }
        float base = s1_lb[tid] + bacc * (1.f / 31.f);
#pragma unroll
        for (int n = 0; n < 32; n++) sO1[n * 256 + tid] = fmaxf(base + acc[n], 0.f);
    }
    __syncthreads();
    {
        float s = 0.f;
#pragma unroll
        for (int n = 0; n < 32; n++) s += sO1[n * 256 + tid];
        sCs[tid] = s;
    }
    __syncthreads();

    // sage2: o2 = tid&127, k-half = tid>>7
    {
        int o2 = tid & 127, half = tid >> 7;
        float acc[32];
#pragma unroll
        for (int n = 0; n < 32; n++) acc[n] = 0.f;
        float bacc = 0.f;
        const float4* lw4 = reinterpret_cast<const float4*>(s2_lw + o2 * 256 + half * 128);
        const float4* rw4 = reinterpret_cast<const float4*>(s2_rw + o2 * 256 + half * 128);
        const float* csb = sCs + half * 128;
        const float* o1b = sO1 + half * 128;
#pragma unroll 2
        for (int k4 = 0; k4 < 32; k4++) {
            float4 lw = lw4[k4], rw = rw4[k4];
            float4 cs = *reinterpret_cast<const float4*>(csb + k4 * 4);
            bacc += cs.x * lw.x + cs.y * lw.y + cs.z * lw.z + cs.w * lw.w;
            float4 wc;
            wc.x = rw.x - lw.x * (1.f / 31.f); wc.y = rw.y - lw.y * (1.f / 31.f);
            wc.z = rw.z - lw.z * (1.f / 31.f); wc.w = rw.w - lw.w * (1.f / 31.f);
#pragma unroll
            for (int n = 0; n < 32; n++) {
                float4 hv = *reinterpret_cast<const float4*>(o1b + n * 256 + k4 * 4);
                acc[n] += wc.x * hv.x + wc.y * hv.y + wc.z * hv.z + wc.w * hv.w;
            }
        }
#pragma unroll
        for (int n = 0; n < 32; n++) sH[n * 256 + tid] = acc[n];
        sB2[tid] = bacc;
    }
    __syncthreads();
    for (int e = tid; e < 4096; e += 256) {
        int n = e >> 7, o2 = e & 127;
        float v = sH[n * 256 + o2] + sH[n * 256 + o2 + 128];
        float base = s2_lb[o2] + (sB2[o2] + sB2[o2 + 128]) * (1.f / 31.f);
        out[(b * 32 + n) * 128 + o2] = base + v;
    }
}

// ---------------- launch ----------------
extern "C" void kernel_launch(void* const* d_in, const int* in_sizes, int n_in,
                              void* d_out, int out_size) {
    const float* x       = (const float*)d_in[0];
    const float* mask    = (const float*)d_in[1];
    const float* conv1_w = (const float*)d_in[2];
    const float* conv1_b = (const float*)d_in[3];
    const float* conv2_w = (const float*)d_in[4];
    const float* conv2_b = (const float*)d_in[5];
    const float* fc_w    = (const float*)d_in[6];
    const float* fc_b    = (const float*)d_in[7];
    const float* s1_lw   = (const float*)d_in[8];
    const float* s1_lb   = (const float*)d_in[9];
    const float* s1_rw   = (const float*)d_in[10];
    const float* s2_lw   = (const float*)d_in[11];
    const float* s2_lb   = (const float*)d_in[12];
    const float* s2_rw   = (const float*)d_in[13];
    float* out = (float*)d_out;

    cudaFuncSetAttribute(conv1_kernel, cudaFuncAttributeMaxDynamicSharedMemorySize, C1_SMEM);
    cudaFuncSetAttribute(conv2_mma_kernel, cudaFuncAttributeMaxDynamicSharedMemorySize,
                         SMEM2_TOTAL);
    cudaFuncSetAttribute(tail_kernel, cudaFuncAttributeMaxDynamicSharedMemorySize, TAIL_SMEM);

    conv1_kernel<<<1024, 256, C1_SMEM>>>(x, conv1_w, conv1_b);
    conv2_mma_kernel<<<148, 512, SMEM2_TOTAL>>>(conv2_w, conv2_b);
    tail_kernel<<<32, 256, TAIL_SMEM>>>(fc_w, fc_b, mask, s1_lw, s1_lb, s1_rw,
                                        s2_lw, s2_lb, s2_rw, out);
}